// round 13
// baseline (speedup 1.0000x reference)
#include <cuda_runtime.h>
#include <math.h>

#define NN   32768
#define EE   262144
#define GG   64
#define NPGG 512
#define KSEL 256
#define CC   10
#define EPSB 1e-5f

// ---------------- device scratch ----------------
__device__ float g_dinv[NN];
__device__ int   g_indeg[NN];
__device__ int   g_off[NN + 1];
__device__ int   g_cur[NN];
__device__ int   g_bsum[128];
__device__ int   g_boff[129];
__device__ int   g_csrc[EE];
__device__ float g_h[NN * 256];
__device__ float g_h2[NN * 256];
__device__ float g_t[NN * 256];
__device__ float g_hf[NN * 768];
__device__ float g_xt[NN * 768];
__device__ float g_splin[NN], g_snlin[NN];
__device__ float g_sp[NN], g_sn[NN];
__device__ unsigned char g_mp[NN], g_mn[NN];
__device__ int   g_list[2 * GG * KSEL];
__device__ int   g_ridx[NN];
__device__ int   g_ucnt;
__device__ float g_e[2 * GG * 1536];
__device__ float g_z[2 * GG * 256], g_aA[2 * GG * 256], g_aB[2 * GG * 256];
__device__ int   g_is64;

__device__ __forceinline__ int ld_idx(const void* p, long long i, int is64) {
    return is64 ? (int)((const long long*)p)[i] : ((const int*)p)[i];
}

// fused: dtype detect + zero indeg
__global__ void k_init(const void* bt, int* indeg) {
    int i = blockIdx.x * blockDim.x + threadIdx.x;
    if (i < NN) indeg[i] = 0;
    if (i == 0) {
        int v = ((const int*)bt)[1025];
        g_is64 = (v == 2) ? 0 : 1;
    }
}
__global__ void k_indeg(const void* __restrict__ ei, int* indeg) {
    int e = blockIdx.x * blockDim.x + threadIdx.x;
    if (e >= EE) return;
    int d = ld_idx(ei, (long long)EE + e, g_is64);
    if ((unsigned)d < NN) atomicAdd(&indeg[d], 1);
}
// ---- hierarchical scan: per-block local scan + dinv + cur zero ----
__global__ void k_scan1(const int* __restrict__ indeg, int* __restrict__ off,
                        int* __restrict__ cur, float* __restrict__ dinv,
                        int* __restrict__ bsum) {
    __shared__ int sh[256];
    int t = threadIdx.x;
    int i = blockIdx.x * 256 + t;
    int v = indeg[i];
    dinv[i] = rsqrtf((float)v + 1.0f);
    cur[i] = 0;
    sh[t] = v;
    __syncthreads();
    for (int o = 1; o < 256; o <<= 1) {
        int add = (t >= o) ? sh[t - o] : 0;
        __syncthreads();
        sh[t] += add;
        __syncthreads();
    }
    off[i] = sh[t] - v;
    if (t == 255) bsum[blockIdx.x] = sh[255];
}
__global__ void k_scan2(const int* __restrict__ bsum, int* __restrict__ boff) {
    __shared__ int sh[128];
    int t = threadIdx.x;
    int v = bsum[t];
    sh[t] = v;
    __syncthreads();
    for (int o = 1; o < 128; o <<= 1) {
        int add = (t >= o) ? sh[t - o] : 0;
        __syncthreads();
        sh[t] += add;
        __syncthreads();
    }
    boff[t] = sh[t] - v;
    if (t == 127) boff[128] = sh[127];
}
__global__ void k_scan3(int* __restrict__ off, const int* __restrict__ boff) {
    int i = blockIdx.x * 256 + threadIdx.x;
    off[i] += boff[blockIdx.x];
    if (i == 0) off[NN] = boff[128];
}
__global__ void k_fill(const void* __restrict__ ei, const int* __restrict__ off,
                       int* __restrict__ cur, int* __restrict__ csrc) {
    int e = blockIdx.x * blockDim.x + threadIdx.x;
    if (e >= EE) return;
    int is64 = g_is64;
    int s = ld_idx(ei, e, is64);
    int d = ld_idx(ei, (long long)EE + e, is64);
    if ((unsigned)s >= NN || (unsigned)d >= NN) return;
    int pos = off[d] + atomicAdd(&cur[d], 1);
    csrc[pos] = s;
}

// ---------------- TF32 GEMM machinery ----------------
__device__ __forceinline__ unsigned f2tf(float f) {
    unsigned u;
    asm("cvt.rna.tf32.f32 %0, %1;" : "=r"(u) : "f"(f));
    return u;
}
__device__ __forceinline__ void split_tf(float v, unsigned& hi, unsigned& lo) {
    hi = f2tf(v);
    lo = f2tf(v - __uint_as_float(hi));
}
#define MMA_TF32(ACC, A0, A1, A2, A3, B0, B1)                                  \
    asm volatile(                                                              \
        "mma.sync.aligned.m16n8k8.row.col.f32.tf32.tf32.f32 "                  \
        "{%0,%1,%2,%3},{%4,%5,%6,%7},{%8,%9},{%0,%1,%2,%3};"                   \
        : "+f"(ACC[0]), "+f"(ACC[1]), "+f"(ACC[2]), "+f"(ACC[3])               \
        : "r"(A0), "r"(A1), "r"(A2), "r"(A3), "r"(B0), "r"(B1))

// ---- tf32x3 layout (hi+lo) ----
#define OFF_ASL 2560
#define OFF_BSH 5120
#define OFF_BSL 7296
#define STG     9472
#define SMEM_BYTES (2 * STG * 4)

__device__ __forceinline__ void stage_chunk(unsigned* sm, int s,
    float4 ra0, float4 ra1, float4 rb0, float4 rb1,
    int arow, int acol, int brow, int bcol)
{
    unsigned* b = sm + s * STG;
    unsigned h0,l0,h1,l1,h2,l2,h3,l3;
    split_tf(ra0.x,h0,l0); split_tf(ra0.y,h1,l1);
    split_tf(ra0.z,h2,l2); split_tf(ra0.w,h3,l3);
    *(uint4*)&b[arow*20 + acol]            = make_uint4(h0,h1,h2,h3);
    *(uint4*)&b[OFF_ASL + arow*20 + acol]  = make_uint4(l0,l1,l2,l3);
    split_tf(ra1.x,h0,l0); split_tf(ra1.y,h1,l1);
    split_tf(ra1.z,h2,l2); split_tf(ra1.w,h3,l3);
    *(uint4*)&b[(arow+64)*20 + acol]           = make_uint4(h0,h1,h2,h3);
    *(uint4*)&b[OFF_ASL + (arow+64)*20 + acol] = make_uint4(l0,l1,l2,l3);
    split_tf(rb0.x,h0,l0); split_tf(rb0.y,h1,l1);
    split_tf(rb0.z,h2,l2); split_tf(rb0.w,h3,l3);
    *(uint4*)&b[OFF_BSH + brow*136 + bcol] = make_uint4(h0,h1,h2,h3);
    *(uint4*)&b[OFF_BSL + brow*136 + bcol] = make_uint4(l0,l1,l2,l3);
    split_tf(rb1.x,h0,l0); split_tf(rb1.y,h1,l1);
    split_tf(rb1.z,h2,l2); split_tf(rb1.w,h3,l3);
    *(uint4*)&b[OFF_BSH + brow*136 + bcol+4] = make_uint4(h0,h1,h2,h3);
    *(uint4*)&b[OFF_BSL + brow*136 + bcol+4] = make_uint4(l0,l1,l2,l3);
}

#define MMA_CHUNK(BASE)                                                        \
    _Pragma("unroll")                                                          \
    for (int kk = 0; kk < 16; kk += 8) {                                       \
        unsigned aH[4][4], aL[4][4], bH[4][2], bL[4][2];                       \
        _Pragma("unroll")                                                      \
        for (int mi = 0; mi < 4; mi++) {                                       \
            int rb = wm * 64 + mi * 16 + (lane >> 2);                          \
            int kc = kk + (lane & 3);                                          \
            aH[mi][0] = BASE[rb*20+kc];             aL[mi][0] = BASE[OFF_ASL+rb*20+kc]; \
            aH[mi][1] = BASE[(rb+8)*20+kc];         aL[mi][1] = BASE[OFF_ASL+(rb+8)*20+kc]; \
            aH[mi][2] = BASE[rb*20+kc+4];           aL[mi][2] = BASE[OFF_ASL+rb*20+kc+4]; \
            aH[mi][3] = BASE[(rb+8)*20+kc+4];       aL[mi][3] = BASE[OFF_ASL+(rb+8)*20+kc+4]; \
        }                                                                      \
        _Pragma("unroll")                                                      \
        for (int ni = 0; ni < 4; ni++) {                                       \
            int cb = wn * 32 + ni * 8 + (lane >> 2);                           \
            int kr = kk + (lane & 3);                                          \
            bH[ni][0] = BASE[OFF_BSH+kr*136+cb];     bL[ni][0] = BASE[OFF_BSL+kr*136+cb]; \
            bH[ni][1] = BASE[OFF_BSH+(kr+4)*136+cb]; bL[ni][1] = BASE[OFF_BSL+(kr+4)*136+cb]; \
        }                                                                      \
        _Pragma("unroll")                                                      \
        for (int mi = 0; mi < 4; mi++)                                         \
            _Pragma("unroll")                                                  \
            for (int ni = 0; ni < 4; ni++) {                                   \
                MMA_TF32(acc[mi][ni], aL[mi][0],aL[mi][1],aL[mi][2],aL[mi][3], \
                         bH[ni][0],bH[ni][1]);                                 \
                MMA_TF32(acc[mi][ni], aH[mi][0],aH[mi][1],aH[mi][2],aH[mi][3], \
                         bL[ni][0],bL[ni][1]);                                 \
                MMA_TF32(acc[mi][ni], aH[mi][0],aH[mi][1],aH[mi][2],aH[mi][3], \
                         bH[ni][0],bH[ni][1]);                                 \
            }                                                                  \
    }

// ---- single-pass tf32 layout (hi only) for pool ----
#define P_BSH 2560
#define P_STG 4736
#define P_SMEM_BYTES (2 * P_STG * 4)

__device__ __forceinline__ void stage_chunk_hi(unsigned* sm, int s,
    float4 ra0, float4 ra1, float4 rb0, float4 rb1,
    int arow, int acol, int brow, int bcol)
{
    unsigned* b = sm + s * P_STG;
    *(uint4*)&b[arow*20 + acol] =
        make_uint4(f2tf(ra0.x), f2tf(ra0.y), f2tf(ra0.z), f2tf(ra0.w));
    *(uint4*)&b[(arow+64)*20 + acol] =
        make_uint4(f2tf(ra1.x), f2tf(ra1.y), f2tf(ra1.z), f2tf(ra1.w));
    *(uint4*)&b[P_BSH + brow*136 + bcol] =
        make_uint4(f2tf(rb0.x), f2tf(rb0.y), f2tf(rb0.z), f2tf(rb0.w));
    *(uint4*)&b[P_BSH + brow*136 + bcol+4] =
        make_uint4(f2tf(rb1.x), f2tf(rb1.y), f2tf(rb1.z), f2tf(rb1.w));
}

#define MMA_CHUNK_1(BASE)                                                      \
    _Pragma("unroll")                                                          \
    for (int kk = 0; kk < 16; kk += 8) {                                       \
        unsigned aH[4][4], bH[4][2];                                           \
        _Pragma("unroll")                                                      \
        for (int mi = 0; mi < 4; mi++) {                                       \
            int rb = wm * 64 + mi * 16 + (lane >> 2);                          \
            int kc = kk + (lane & 3);                                          \
            aH[mi][0] = BASE[rb*20+kc];                                        \
            aH[mi][1] = BASE[(rb+8)*20+kc];                                    \
            aH[mi][2] = BASE[rb*20+kc+4];                                      \
            aH[mi][3] = BASE[(rb+8)*20+kc+4];                                  \
        }                                                                      \
        _Pragma("unroll")                                                      \
        for (int ni = 0; ni < 4; ni++) {                                       \
            int cb = wn * 32 + ni * 8 + (lane >> 2);                           \
            int kr = kk + (lane & 3);                                          \
            bH[ni][0] = BASE[P_BSH+kr*136+cb];                                 \
            bH[ni][1] = BASE[P_BSH+(kr+4)*136+cb];                             \
        }                                                                      \
        _Pragma("unroll")                                                      \
        for (int mi = 0; mi < 4; mi++)                                         \
            _Pragma("unroll")                                                  \
            for (int ni = 0; ni < 4; ni++)                                     \
                MMA_TF32(acc[mi][ni], aH[mi][0],aH[mi][1],aH[mi][2],aH[mi][3], \
                         bH[ni][0],bH[ni][1]);                                 \
    }

// fused front GEMM: raw outputs only
__global__ void __launch_bounds__(256, 2)
gemm_front(const float* __restrict__ x,
           const float* __restrict__ w_s1,
           const float* __restrict__ w_s21,
           const float* __restrict__ w_raw, const float* __restrict__ b_raw,
           float* __restrict__ h1, float* __restrict__ h2,
           float* __restrict__ hf)
{
    extern __shared__ unsigned sm[];
    int sel  = blockIdx.x >> 1;
    int xcol = blockIdx.x & 1;
    const float* Bsel = (sel == 0) ? w_s1 : (sel == 1) ? w_s21 : w_raw;

    int tid  = threadIdx.x;
    int lane = tid & 31;
    int warp = tid >> 5;
    int wm = warp >> 2, wn = warp & 3;

    float acc[4][4][4];
#pragma unroll
    for (int mi = 0; mi < 4; mi++)
#pragma unroll
        for (int ni = 0; ni < 4; ni++)
#pragma unroll
            for (int r = 0; r < 4; r++) acc[mi][ni][r] = 0.0f;

    const float* Ab = x + (size_t)(blockIdx.y * 128) * 256;
    const float* Bb = Bsel + xcol * 128;

    int arow = tid >> 2, acol = (tid & 3) * 4;
    int brow = tid >> 4, bcol = (tid & 15) * 8;

    float4 ra0, ra1, rb0, rb1;
#define LOADF(K0)                                                               \
    ra0 = *(const float4*)(Ab + (size_t)arow * 256 + (K0) + acol);              \
    ra1 = *(const float4*)(Ab + (size_t)(arow + 64) * 256 + (K0) + acol);       \
    rb0 = *(const float4*)(Bb + (size_t)((K0) + brow) * 256 + bcol);            \
    rb1 = *(const float4*)(Bb + (size_t)((K0) + brow) * 256 + bcol + 4);

    LOADF(0)
    stage_chunk(sm, 0, ra0, ra1, rb0, rb1, arow, acol, brow, bcol);
    __syncthreads();
    int p = 0;
    for (int k0 = 0; k0 < 256; k0 += 16) {
        bool nxt = (k0 + 16) < 256;
        if (nxt) { LOADF(k0 + 16) }
        const unsigned* base = sm + p * STG;
        MMA_CHUNK(base)
        if (nxt) {
            stage_chunk(sm, p ^ 1, ra0, ra1, rb0, rb1, arow, acol, brow, bcol);
            __syncthreads();
        }
        p ^= 1;
    }

    int rbase = blockIdx.y * 128 + wm * 64 + (lane >> 2);
    int cloc  = xcol * 128 + wn * 32 + (lane & 3) * 2;
#pragma unroll
    for (int mi = 0; mi < 4; mi++)
#pragma unroll
        for (int ni = 0; ni < 4; ni++)
#pragma unroll
            for (int r = 0; r < 4; r++) {
                int row = rbase + mi * 16 + ((r >> 1) ? 8 : 0);
                int col = cloc + ni * 8 + (r & 1);
                float v = acc[mi][ni][r];
                if (sel == 0)      h1[(size_t)row * 256 + col] = v;
                else if (sel == 1) h2[(size_t)row * 256 + col] = v;
                else               hf[(size_t)row * 768 + 512 + col] = v + b_raw[col];
            }
}

// generic tf32x3, raw output only
__global__ void __launch_bounds__(256, 2)
gemm_tf32x3(const float* __restrict__ A, const float* __restrict__ B,
            float* __restrict__ C, int Nn, int Kk, int ldc)
{
    extern __shared__ unsigned sm[];
    int tid  = threadIdx.x;
    int lane = tid & 31;
    int warp = tid >> 5;
    int wm = warp >> 2, wn = warp & 3;

    float acc[4][4][4];
#pragma unroll
    for (int mi = 0; mi < 4; mi++)
#pragma unroll
        for (int ni = 0; ni < 4; ni++)
#pragma unroll
            for (int r = 0; r < 4; r++) acc[mi][ni][r] = 0.0f;

    const float* Ab = A + (size_t)(blockIdx.y * 128) * Kk;
    const float* Bb = B + blockIdx.x * 128;

    int arow = tid >> 2, acol = (tid & 3) * 4;
    int brow = tid >> 4, bcol = (tid & 15) * 8;

    float4 ra0, ra1, rb0, rb1;
#define LOADG(K0)                                                               \
    ra0 = *(const float4*)(Ab + (size_t)arow * Kk + (K0) + acol);               \
    ra1 = *(const float4*)(Ab + (size_t)(arow + 64) * Kk + (K0) + acol);        \
    rb0 = *(const float4*)(Bb + (size_t)((K0) + brow) * Nn + bcol);             \
    rb1 = *(const float4*)(Bb + (size_t)((K0) + brow) * Nn + bcol + 4);

    LOADG(0)
    stage_chunk(sm, 0, ra0, ra1, rb0, rb1, arow, acol, brow, bcol);
    __syncthreads();
    int p = 0;
    for (int k0 = 0; k0 < Kk; k0 += 16) {
        bool nxt = (k0 + 16) < Kk;
        if (nxt) { LOADG(k0 + 16) }
        const unsigned* base = sm + p * STG;
        MMA_CHUNK(base)
        if (nxt) {
            stage_chunk(sm, p ^ 1, ra0, ra1, rb0, rb1, arow, acol, brow, bcol);
            __syncthreads();
        }
        p ^= 1;
    }

    int rbase = blockIdx.y * 128 + wm * 64 + (lane >> 2);
    int cbase = blockIdx.x * 128 + wn * 32 + (lane & 3) * 2;
#pragma unroll
    for (int mi = 0; mi < 4; mi++)
#pragma unroll
        for (int ni = 0; ni < 4; ni++)
#pragma unroll
            for (int r = 0; r < 4; r++) {
                int row = rbase + mi * 16 + ((r >> 1) ? 8 : 0);
                int col = cbase + ni * 8 + (r & 1);
                C[(size_t)row * ldc + col] = acc[mi][ni][r];
            }
}

// masked pool GEMM — single-pass tf32 (post-topk, continuous consumers only)
__global__ void __launch_bounds__(256, 2)
gemm_pool(const float* __restrict__ hf, const float* __restrict__ B,
          const float* __restrict__ bias, float* __restrict__ xt,
          const int* __restrict__ ridx, const int* __restrict__ pcnt)
{
    extern __shared__ unsigned sm[];
    int cnt = *pcnt;
    if ((int)(blockIdx.y * 128) >= cnt) return;

    int tid  = threadIdx.x;
    int lane = tid & 31;
    int warp = tid >> 5;
    int wm = warp >> 2, wn = warp & 3;

    float acc[4][4][4];
#pragma unroll
    for (int mi = 0; mi < 4; mi++)
#pragma unroll
        for (int ni = 0; ni < 4; ni++)
#pragma unroll
            for (int r = 0; r < 4; r++) acc[mi][ni][r] = 0.0f;

    int arow = tid >> 2, acol = (tid & 3) * 4;
    int brow = tid >> 4, bcol = (tid & 15) * 8;

    int gr0 = blockIdx.y * 128 + arow;
    int gr1 = gr0 + 64;
    const float* Ar0 = hf + (size_t)ridx[gr0 < cnt ? gr0 : cnt - 1] * 768;
    const float* Ar1 = hf + (size_t)ridx[gr1 < cnt ? gr1 : cnt - 1] * 768;
    const float* Bb = B + blockIdx.x * 128;

    float4 ra0, ra1, rb0, rb1;
#define LOADP(K0)                                                               \
    ra0 = *(const float4*)(Ar0 + (K0) + acol);                                  \
    ra1 = *(const float4*)(Ar1 + (K0) + acol);                                  \
    rb0 = *(const float4*)(Bb + (size_t)((K0) + brow) * 768 + bcol);            \
    rb1 = *(const float4*)(Bb + (size_t)((K0) + brow) * 768 + bcol + 4);

    LOADP(0)
    stage_chunk_hi(sm, 0, ra0, ra1, rb0, rb1, arow, acol, brow, bcol);
    __syncthreads();
    int p = 0;
    for (int k0 = 0; k0 < 768; k0 += 16) {
        bool nxt = (k0 + 16) < 768;
        if (nxt) { LOADP(k0 + 16) }
        const unsigned* base = sm + p * P_STG;
        MMA_CHUNK_1(base)
        if (nxt) {
            stage_chunk_hi(sm, p ^ 1, ra0, ra1, rb0, rb1, arow, acol, brow, bcol);
            __syncthreads();
        }
        p ^= 1;
    }

    int rbase = blockIdx.y * 128 + wm * 64 + (lane >> 2);
    int cbase = blockIdx.x * 128 + wn * 32 + (lane & 3) * 2;
#pragma unroll
    for (int mi = 0; mi < 4; mi++)
#pragma unroll
        for (int ni = 0; ni < 4; ni++)
#pragma unroll
            for (int r = 0; r < 4; r++) {
                int rg = rbase + mi * 16 + ((r >> 1) ? 8 : 0);
                int col = cbase + ni * 8 + (r & 1);
                if (rg < cnt) {
                    float v = acc[mi][ni][r] + bias[col];
                    v = 1.0f / (1.0f + expf(-v));
                    xt[(size_t)ridx[rg] * 768 + col] = v;
                }
            }
}

// ---------------- CSR aggregation (float4, self-term + bias + lrelu fused) ----------------
#define F4FMA(A, U, S) { (A).x += (U).x*(S); (A).y += (U).y*(S); (A).z += (U).z*(S); (A).w += (U).w*(S); }
__device__ __forceinline__ float lrelu1(float v) { return v > 0.0f ? v : 0.01f * v; }

__global__ void k_agg_csr2(const float* __restrict__ h1, const float* __restrict__ h2,
                           const int* __restrict__ off, const int* __restrict__ csrc,
                           const float* __restrict__ dinv,
                           const float* __restrict__ b1v, const float* __restrict__ b2v,
                           float* __restrict__ o1, float* __restrict__ o2) {
    int n = blockIdx.x * 8 + (threadIdx.x >> 5);
    int lane = threadIdx.x & 31;
    int c0 = lane * 8;
    float4 A1a = {0,0,0,0}, A1b = {0,0,0,0}, A2a = {0,0,0,0}, A2b = {0,0,0,0};
    int beg = off[n], end = off[n + 1];
    float dn = dinv[n];
    for (int j = beg; j < end; j++) {
        int s = csrc[j];
        float nrm = dn * dinv[s];
        const float4* r1 = (const float4*)(h1 + (size_t)s * 256 + c0);
        const float4* r2 = (const float4*)(h2 + (size_t)s * 256 + c0);
        float4 u0 = __ldg(r1), u1 = __ldg(r1 + 1);
        float4 v0 = __ldg(r2), v1 = __ldg(r2 + 1);
        F4FMA(A1a, u0, nrm); F4FMA(A1b, u1, nrm);
        F4FMA(A2a, v0, nrm); F4FMA(A2b, v1, nrm);
    }
    float dn2 = dn * dn;
    const float4* s1 = (const float4*)(h1 + (size_t)n * 256 + c0);
    const float4* s2 = (const float4*)(h2 + (size_t)n * 256 + c0);
    float4 x0 = __ldg(s1), x1 = __ldg(s1 + 1);
    float4 y0 = __ldg(s2), y1 = __ldg(s2 + 1);
    float4 ba0 = __ldg((const float4*)(b1v + c0)), ba1 = __ldg((const float4*)(b1v + c0 + 4));
    float4 bb0 = __ldg((const float4*)(b2v + c0)), bb1 = __ldg((const float4*)(b2v + c0 + 4));
    float4 o;
    o.x = lrelu1(x0.x*dn2 + ba0.x + A1a.x); o.y = lrelu1(x0.y*dn2 + ba0.y + A1a.y);
    o.z = lrelu1(x0.z*dn2 + ba0.z + A1a.z); o.w = lrelu1(x0.w*dn2 + ba0.w + A1a.w);
    *(float4*)(o1 + (size_t)n * 768 + c0) = o;
    o.x = lrelu1(x1.x*dn2 + ba1.x + A1b.x); o.y = lrelu1(x1.y*dn2 + ba1.y + A1b.y);
    o.z = lrelu1(x1.z*dn2 + ba1.z + A1b.z); o.w = lrelu1(x1.w*dn2 + ba1.w + A1b.w);
    *(float4*)(o1 + (size_t)n * 768 + c0 + 4) = o;
    o.x = lrelu1(y0.x*dn2 + bb0.x + A2a.x); o.y = lrelu1(y0.y*dn2 + bb0.y + A2a.y);
    o.z = lrelu1(y0.z*dn2 + bb0.z + A2a.z); o.w = lrelu1(y0.w*dn2 + bb0.w + A2a.w);
    *(float4*)(o2 + (size_t)n * 256 + c0) = o;
    o.x = lrelu1(y1.x*dn2 + bb1.x + A2b.x); o.y = lrelu1(y1.y*dn2 + bb1.y + A2b.y);
    o.z = lrelu1(y1.z*dn2 + bb1.z + A2b.z); o.w = lrelu1(y1.w*dn2 + bb1.w + A2b.w);
    *(float4*)(o2 + (size_t)n * 256 + c0 + 4) = o;
}
__global__ void k_agg_csr(const float* __restrict__ h, const int* __restrict__ off,
                          const int* __restrict__ csrc, const float* __restrict__ dinv,
                          const float* __restrict__ bv,
                          float* __restrict__ outp, int ldc) {
    int n = blockIdx.x * 8 + (threadIdx.x >> 5);
    int lane = threadIdx.x & 31;
    int c0 = lane * 8;
    float4 Aa = {0,0,0,0}, Ab4 = {0,0,0,0};
    int beg = off[n], end = off[n + 1];
    float dn = dinv[n];
    for (int j = beg; j < end; j++) {
        int s = csrc[j];
        float nrm = dn * dinv[s];
        const float4* r = (const float4*)(h + (size_t)s * 256 + c0);
        float4 u0 = __ldg(r), u1 = __ldg(r + 1);
        F4FMA(Aa, u0, nrm); F4FMA(Ab4, u1, nrm);
    }
    float dn2 = dn * dn;
    const float4* sp = (const float4*)(h + (size_t)n * 256 + c0);
    float4 x0 = __ldg(sp), x1 = __ldg(sp + 1);
    float4 b0 = __ldg((const float4*)(bv + c0)), b1 = __ldg((const float4*)(bv + c0 + 4));
    float4 o;
    o.x = lrelu1(x0.x*dn2 + b0.x + Aa.x); o.y = lrelu1(x0.y*dn2 + b0.y + Aa.y);
    o.z = lrelu1(x0.z*dn2 + b0.z + Aa.z); o.w = lrelu1(x0.w*dn2 + b0.w + Aa.w);
    *(float4*)(outp + (size_t)n * ldc + c0) = o;
    o.x = lrelu1(x1.x*dn2 + b1.x + Ab4.x); o.y = lrelu1(x1.y*dn2 + b1.y + Ab4.y);
    o.z = lrelu1(x1.z*dn2 + b1.z + Ab4.z); o.w = lrelu1(x1.w*dn2 + b1.w + Ab4.w);
    *(float4*)(outp + (size_t)n * ldc + c0 + 4) = o;
}

// ---------------- score path ----------------
__global__ void k_scorelin(const float* __restrict__ hf, const float* __restrict__ wpos,
                           const float* __restrict__ wneg,
                           float* __restrict__ splin, float* __restrict__ snlin) {
    __shared__ float swp[768], swn[768];
    for (int i = threadIdx.x; i < 768; i += blockDim.x) { swp[i] = wpos[i]; swn[i] = wneg[i]; }
    __syncthreads();
    int node = blockIdx.x * 8 + (threadIdx.x >> 5);
    int lane = threadIdx.x & 31;
    const float* r = hf + (size_t)node * 768;
    float sp = 0.0f, sn = 0.0f;
    for (int k = lane; k < 768; k += 32) {
        float v = r[k];
        sp += v * swp[k]; sn += v * swn[k];
    }
#pragma unroll
    for (int o = 16; o; o >>= 1) {
        sp += __shfl_down_sync(0xffffffffu, sp, o);
        sn += __shfl_down_sync(0xffffffffu, sn, o);
    }
    if (lane == 0) { splin[node] = sp; snlin[node] = sn; }
}
__global__ void k_score_csr(const float* __restrict__ splin, const float* __restrict__ snlin,
                            const int* __restrict__ off, const int* __restrict__ csrc,
                            const float* __restrict__ dinv,
                            const float* __restrict__ bpos, const float* __restrict__ bneg,
                            float* sp, float* sn, float* outp, float* outn) {
    int i = blockIdx.x * blockDim.x + threadIdx.x;
    if (i >= NN) return;
    float di = dinv[i];
    float vp = splin[i] * di * di + bpos[0];
    float vn = snlin[i] * di * di + bneg[0];
    int beg = off[i], end = off[i + 1];
    for (int j = beg; j < end; j++) {
        int s = csrc[j];
        float nrm = di * dinv[s];
        vp += splin[s] * nrm;
        vn += snlin[s] * nrm;
    }
    vp = 1.0f / (1.0f + expf(-vp));
    vn = 1.0f / (1.0f + expf(-vn));
    sp[i] = vp; sn[i] = vn;
    outp[i] = vp; outn[i] = vn;
}

// ---------------- top-k: masks + index lists ----------------
__global__ void k_topk(const float* __restrict__ spv, const float* __restrict__ snv,
                       unsigned char* __restrict__ mp, unsigned char* __restrict__ mn,
                       int* __restrict__ lists) {
    __shared__ float sv[NPGG];
    __shared__ int si[NPGG];
    int which = blockIdx.x >> 6;
    int g = blockIdx.x & 63;
    const float* score = which ? snv : spv;
    unsigned char* mask = which ? mn : mp;
    int t = threadIdx.x;
    sv[t] = score[g * NPGG + t];
    si[t] = t;
    __syncthreads();
    for (int k = 2; k <= NPGG; k <<= 1) {
        for (int j = k >> 1; j > 0; j >>= 1) {
            int ixj = t ^ j;
            if (ixj > t) {
                float va = sv[t], vb = sv[ixj];
                int ia = si[t], ib = si[ixj];
                bool firstBefore = (va > vb) || (va == vb && ia < ib);
                bool dirFwd = ((t & k) == 0);
                if (dirFwd ? !firstBefore : firstBefore) {
                    sv[t] = vb; sv[ixj] = va;
                    si[t] = ib; si[ixj] = ia;
                }
            }
            __syncthreads();
        }
    }
    mask[g * NPGG + si[t]] = (t < KSEL) ? 1 : 0;
    if (t < KSEL) lists[(which * GG + g) * KSEL + t] = si[t];
}

// ---------------- union compaction ----------------
__global__ void k_union(const unsigned char* __restrict__ mp,
                        const unsigned char* __restrict__ mn,
                        int* __restrict__ ridx, int* __restrict__ ucnt) {
    __shared__ int part[1024];
    int t = threadIdx.x;
    int base = t * 32;
    int sum = 0;
#pragma unroll
    for (int i = 0; i < 32; i++) sum += (mp[base + i] | mn[base + i]) ? 1 : 0;
    part[t] = sum;
    __syncthreads();
    for (int o = 1; o < 1024; o <<= 1) {
        int v = (t >= o) ? part[t - o] : 0;
        __syncthreads();
        part[t] += v;
        __syncthreads();
    }
    int pos = part[t] - sum;
#pragma unroll
    for (int i = 0; i < 32; i++)
        if (mp[base + i] | mn[base + i]) ridx[pos++] = base + i;
    if (t == 1023) *ucnt = part[1023];
}

// ---------------- readout via index lists ----------------
__global__ void k_readout(const float* __restrict__ xt, const int* __restrict__ lists,
                          float* __restrict__ eb) {
    __shared__ int sidx[KSEL];
    int z = blockIdx.z;
    int g = blockIdx.x;
    int f = blockIdx.y * 128 + threadIdx.x;
    const int* lst = lists + (z * GG + g) * KSEL;
    for (int i = threadIdx.x; i < KSEL; i += 128) sidx[i] = lst[i];
    __syncthreads();
    float* e = eb + z * (GG * 1536);
    float sum = 0.0f, mx = -INFINITY;
    const float* basep = xt + (size_t)g * NPGG * 768 + f;
    for (int n = 0; n < KSEL; n++) {
        float v = basep[(size_t)sidx[n] * 768];
        sum += v;
        mx = fmaxf(mx, v);
    }
    e[g * 1536 + f] = sum * (1.0f / (float)KSEL);
    e[g * 1536 + 768 + f] = mx;
}

// ---------------- MLP (batched pos/neg) ----------------
__global__ void k_mlp_lin(const float* __restrict__ inb, int in_set_stride,
                          const float* __restrict__ W, const float* __restrict__ b,
                          float* __restrict__ outb, int Kin, int Nout) {
    __shared__ float s_in[1536];
    int set = blockIdx.y;
    int row = blockIdx.x;
    const float* in = inb + (size_t)set * in_set_stride + (size_t)row * Kin;
    for (int k = threadIdx.x; k < Kin; k += blockDim.x) s_in[k] = in[k];
    __syncthreads();
    int j = threadIdx.x;
    if (j < Nout) {
        float s = b[j];
        for (int k = 0; k < Kin; k++) s += s_in[k] * W[k * Nout + j];
        outb[(size_t)(set * GG + row) * Nout + j] = s;
    }
}
__global__ void k_bn_relu(const float* __restrict__ zb, const float* __restrict__ g,
                          const float* __restrict__ be, const float* __restrict__ resb,
                          float* __restrict__ outb) {
    int c = blockIdx.x, r = threadIdx.x, set = blockIdx.y;
    const float* z = zb + (size_t)set * GG * 256;
    float v = z[r * 256 + c];
    __shared__ float sh[64];
    sh[r] = v; __syncthreads();
    for (int o = 32; o; o >>= 1) { if (r < o) sh[r] += sh[r + o]; __syncthreads(); }
    float mean = sh[0] * (1.0f / 64.0f);
    __syncthreads();
    sh[r] = v * v; __syncthreads();
    for (int o = 32; o; o >>= 1) { if (r < o) sh[r] += sh[r + o]; __syncthreads(); }
    float var = sh[0] * (1.0f / 64.0f) - mean * mean;
    float y = (v - mean) * rsqrtf(var + EPSB) * g[c] + be[c];
    y = fmaxf(y, 0.0f);
    if (resb) y += resb[(size_t)set * GG * 256 + r * 256 + c];
    outb[(size_t)set * GG * 256 + r * 256 + c] = y;
}
__global__ void k_logits_softmax(const float* __restrict__ ab, const float* __restrict__ w4,
                                 const float* __restrict__ b4,
                                 float* __restrict__ logits_pos,
                                 float* __restrict__ probs_pos,
                                 float* __restrict__ probs_neg) {
    int set = blockIdx.y;
    int row = blockIdx.x, j = threadIdx.x;
    const float* a = ab + (size_t)set * GG * 256;
    __shared__ float sl[CC];
    if (j < CC) {
        float s = b4[j];
        for (int k = 0; k < 256; k++) s += a[row * 256 + k] * w4[k * CC + j];
        sl[j] = s;
        if (set == 0) logits_pos[row * CC + j] = s;
    }
    __syncthreads();
    if (j < CC) {
        float mx = sl[0];
        for (int t = 1; t < CC; t++) mx = fmaxf(mx, sl[t]);
        float sum = 0.0f;
        for (int t = 0; t < CC; t++) sum += expf(sl[t] - mx);
        float pv = expf(sl[j] - mx) / sum;
        if (set == 0) probs_pos[row * CC + j] = pv;
        else          probs_neg[row * CC + j] = pv;
    }
}
__global__ void k_batch_out(const void* __restrict__ bt, float* __restrict__ out) {
    int i = blockIdx.x * blockDim.x + threadIdx.x;
    if (i < NN) out[i] = (float)ld_idx(bt, i, g_is64);
}

// ---------------- host driver ----------------
static void* sym(const void* s) { void* p = nullptr; cudaGetSymbolAddress(&p, s); return p; }

extern "C" void kernel_launch(void* const* d_in, const int* in_sizes, int n_in,
                              void* d_out, int out_size) {
    const float* x     = (const float*)d_in[0];
    const void*  ei    = d_in[1];
    const void*  bt    = d_in[2];
    const float* w_s1  = (const float*)d_in[3];  const float* b_s1  = (const float*)d_in[4];
    const float* w_s21 = (const float*)d_in[5];  const float* b_s21 = (const float*)d_in[6];
    const float* w_s22 = (const float*)d_in[7];  const float* b_s22 = (const float*)d_in[8];
    const float* w_raw = (const float*)d_in[9];  const float* b_raw = (const float*)d_in[10];
    const float* w_pos = (const float*)d_in[11]; const float* b_pos = (const float*)d_in[12];
    const float* w_neg = (const float*)d_in[13]; const float* b_neg = (const float*)d_in[14];
    const float* w_pool= (const float*)d_in[15]; const float* b_pool= (const float*)d_in[16];
    const float* w1 = (const float*)d_in[17]; const float* b1 = (const float*)d_in[18];
    const float* g1 = (const float*)d_in[19]; const float* be1= (const float*)d_in[20];
    const float* w2 = (const float*)d_in[21]; const float* b2 = (const float*)d_in[22];
    const float* g2 = (const float*)d_in[23]; const float* be2= (const float*)d_in[24];
    const float* w3 = (const float*)d_in[25]; const float* b3 = (const float*)d_in[26];
    const float* g3 = (const float*)d_in[27]; const float* be3= (const float*)d_in[28];
    const float* w4 = (const float*)d_in[29]; const float* b4 = (const float*)d_in[30];

    float* dinv = (float*)sym(g_dinv);
    int* indeg  = (int*)sym(g_indeg);
    int* off    = (int*)sym(g_off);
    int* cur    = (int*)sym(g_cur);
    int* bsum   = (int*)sym(g_bsum);
    int* boff   = (int*)sym(g_boff);
    int* csrc   = (int*)sym(g_csrc);
    float* hbuf = (float*)sym(g_h);
    float* hbuf2= (float*)sym(g_h2);
    float* tbuf = (float*)sym(g_t);
    float* hf   = (float*)sym(g_hf);
    float* xt   = (float*)sym(g_xt);
    float* splin= (float*)sym(g_splin);
    float* snlin= (float*)sym(g_snlin);
    float* spv  = (float*)sym(g_sp);
    float* snv  = (float*)sym(g_sn);
    unsigned char* mp = (unsigned char*)sym(g_mp);
    unsigned char* mn = (unsigned char*)sym(g_mn);
    int* lists  = (int*)sym(g_list);
    int* ridx   = (int*)sym(g_ridx);
    int* ucnt   = (int*)sym(&g_ucnt);
    float* eb   = (float*)sym(g_e);
    float* zb   = (float*)sym(g_z);
    float* aA   = (float*)sym(g_aA);
    float* aB   = (float*)sym(g_aB);

    float* out = (float*)d_out;
    float* out_logits_pos = out;
    float* out_probs_pos  = out + 640;
    float* out_probs_neg  = out + 1280;
    float* out_score_pos  = out + 1920;
    float* out_score_neg  = out + 1920 + NN;
    float* out_batch      = out + 1920 + 2 * NN;

    cudaFuncSetAttribute(gemm_front,  cudaFuncAttributeMaxDynamicSharedMemorySize, SMEM_BYTES);
    cudaFuncSetAttribute(gemm_tf32x3, cudaFuncAttributeMaxDynamicSharedMemorySize, SMEM_BYTES);
    cudaFuncSetAttribute(gemm_pool,   cudaFuncAttributeMaxDynamicSharedMemorySize, P_SMEM_BYTES);

    // detect dtype + zero indeg (fused)
    k_init<<<NN / 256, 256>>>(bt, indeg);

    // fused front GEMM (independent of CSR)
    dim3 gF(6, 256);
    gemm_front<<<gF, 256, SMEM_BYTES>>>(x, w_s1, w_s21, w_raw, b_raw, hbuf, hbuf2, hf);

    // CSR build (hierarchical scan)
    k_indeg<<<EE / 256, 256>>>(ei, indeg);
    k_scan1<<<128, 256>>>(indeg, off, cur, dinv, bsum);
    k_scan2<<<1, 128>>>(bsum, boff);
    k_scan3<<<128, 256>>>(off, boff);
    k_fill<<<EE / 256, 256>>>(ei, off, cur, csrc);

    // dual aggregation (self-term + bias + lrelu fused, float4)
    k_agg_csr2<<<NN / 8, 256>>>(hbuf, hbuf2, off, csrc, dinv, b_s1, b_s21, hf, tbuf);

    // s22 GEMM + aggregation
    dim3 gB256(2, 256);
    gemm_tf32x3<<<gB256, 256, SMEM_BYTES>>>(tbuf, w_s22, hbuf, 256, 256, 256);
    k_agg_csr<<<NN / 8, 256>>>(hbuf, off, csrc, dinv, b_s22, hf + 256, 768);

    // scores -> topk (+lists) -> union
    k_scorelin<<<NN / 8, 256>>>(hf, w_pos, w_neg, splin, snlin);
    k_score_csr<<<NN / 256, 256>>>(splin, snlin, off, csrc, dinv, b_pos, b_neg,
                                   spv, snv, out_score_pos, out_score_neg);
    k_topk<<<128, NPGG>>>(spv, snv, mp, mn, lists);
    k_union<<<1, 1024>>>(mp, mn, ridx, ucnt);

    // masked pool GEMM (single-pass tf32)
    dim3 gP(6, 256);
    gemm_pool<<<gP, 256, P_SMEM_BYTES>>>(hf, w_pool, b_pool, xt, ridx, ucnt);

    // readout via lists
    dim3 gr(GG, 6, 2);
    k_readout<<<gr, 128>>>(xt, lists, eb);

    // MLP (batched pos/neg)
    dim3 gl(GG, 2), gb(256, 2);
    k_mlp_lin<<<gl, 256>>>(eb, GG * 1536, w1, b1, zb, 1536, 256);
    k_bn_relu<<<gb, 64>>>(zb, g1, be1, nullptr, aA);
    k_mlp_lin<<<gl, 256>>>(aA, GG * 256, w2, b2, zb, 256, 256);
    k_bn_relu<<<gb, 64>>>(zb, g2, be2, aA, aB);
    k_mlp_lin<<<gl, 256>>>(aB, GG * 256, w3, b3, zb, 256, 256);
    k_bn_relu<<<gb, 64>>>(zb, g3, be3, aB, aA);
    k_logits_softmax<<<gl, 32>>>(aA, w4, b4, out_logits_pos, out_probs_pos, out_probs_neg);

    k_batch_out<<<NN / 256, 256>>>(bt, out_batch);
}

// round 14
// speedup vs baseline: 1.4655x; 1.4655x over previous
#include <cuda_runtime.h>
#include <math.h>

#define NN   32768
#define EE   262144
#define GG   64
#define NPGG 512
#define KSEL 256
#define CC   10
#define EPSB 1e-5f

// ---------------- device scratch ----------------
__device__ float g_dinv[NN];
__device__ int   g_indeg[NN];
__device__ int   g_off[NN + 1];
__device__ int   g_cur[NN];
__device__ int   g_bsum[128];
__device__ int   g_boff[129];
__device__ int   g_csrc[EE];
__device__ float g_h[NN * 256];
__device__ float g_h2[NN * 256];
__device__ float g_t[NN * 256];
__device__ float g_hf[NN * 768];
__device__ float g_xt[NN * 768];
__device__ float g_splin[NN], g_snlin[NN];
__device__ float g_sp[NN], g_sn[NN];
__device__ unsigned char g_mp[NN], g_mn[NN];
__device__ int   g_list[2 * GG * KSEL];
__device__ int   g_ridx[NN];
__device__ int   g_ucnt;
__device__ float g_e[2 * GG * 1536];
__device__ float g_z[2 * GG * 256], g_aA[2 * GG * 256], g_aB[2 * GG * 256];
__device__ int   g_is64;

__device__ __forceinline__ int ld_idx(const void* p, long long i, int is64) {
    return is64 ? (int)((const long long*)p)[i] : ((const int*)p)[i];
}

// fused: dtype detect + zero indeg
__global__ void k_init(const void* bt, int* indeg) {
    int i = blockIdx.x * blockDim.x + threadIdx.x;
    if (i < NN) indeg[i] = 0;
    if (i == 0) {
        int v = ((const int*)bt)[1025];
        g_is64 = (v == 2) ? 0 : 1;
    }
}
__global__ void k_batch_out(const void* __restrict__ bt, float* __restrict__ out) {
    int i = blockIdx.x * blockDim.x + threadIdx.x;
    if (i < NN) out[i] = (float)ld_idx(bt, i, g_is64);
}
__global__ void k_indeg(const void* __restrict__ ei, int* indeg) {
    int e = blockIdx.x * blockDim.x + threadIdx.x;
    if (e >= EE) return;
    int d = ld_idx(ei, (long long)EE + e, g_is64);
    if ((unsigned)d < NN) atomicAdd(&indeg[d], 1);
}
// ---- hierarchical scan ----
__global__ void k_scan1(const int* __restrict__ indeg, int* __restrict__ off,
                        int* __restrict__ cur, float* __restrict__ dinv,
                        int* __restrict__ bsum) {
    __shared__ int sh[256];
    int t = threadIdx.x;
    int i = blockIdx.x * 256 + t;
    int v = indeg[i];
    dinv[i] = rsqrtf((float)v + 1.0f);
    cur[i] = 0;
    sh[t] = v;
    __syncthreads();
    for (int o = 1; o < 256; o <<= 1) {
        int add = (t >= o) ? sh[t - o] : 0;
        __syncthreads();
        sh[t] += add;
        __syncthreads();
    }
    off[i] = sh[t] - v;
    if (t == 255) bsum[blockIdx.x] = sh[255];
}
__global__ void k_scan2(const int* __restrict__ bsum, int* __restrict__ boff) {
    __shared__ int sh[128];
    int t = threadIdx.x;
    int v = bsum[t];
    sh[t] = v;
    __syncthreads();
    for (int o = 1; o < 128; o <<= 1) {
        int add = (t >= o) ? sh[t - o] : 0;
        __syncthreads();
        sh[t] += add;
        __syncthreads();
    }
    boff[t] = sh[t] - v;
    if (t == 127) boff[128] = sh[127];
}
__global__ void k_scan3(int* __restrict__ off, const int* __restrict__ boff) {
    int i = blockIdx.x * 256 + threadIdx.x;
    off[i] += boff[blockIdx.x];
    if (i == 0) off[NN] = boff[128];
}
__global__ void k_fill(const void* __restrict__ ei, const int* __restrict__ off,
                       int* __restrict__ cur, int* __restrict__ csrc) {
    int e = blockIdx.x * blockDim.x + threadIdx.x;
    if (e >= EE) return;
    int is64 = g_is64;
    int s = ld_idx(ei, e, is64);
    int d = ld_idx(ei, (long long)EE + e, is64);
    if ((unsigned)s >= NN || (unsigned)d >= NN) return;
    int pos = off[d] + atomicAdd(&cur[d], 1);
    csrc[pos] = s;
}

// ---------------- TF32 GEMM machinery ----------------
__device__ __forceinline__ unsigned f2tf(float f) {
    unsigned u;
    asm("cvt.rna.tf32.f32 %0, %1;" : "=r"(u) : "f"(f));
    return u;
}
__device__ __forceinline__ void split_tf(float v, unsigned& hi, unsigned& lo) {
    hi = f2tf(v);
    lo = f2tf(v - __uint_as_float(hi));
}
#define MMA_TF32(ACC, A0, A1, A2, A3, B0, B1)                                  \
    asm volatile(                                                              \
        "mma.sync.aligned.m16n8k8.row.col.f32.tf32.tf32.f32 "                  \
        "{%0,%1,%2,%3},{%4,%5,%6,%7},{%8,%9},{%0,%1,%2,%3};"                   \
        : "+f"(ACC[0]), "+f"(ACC[1]), "+f"(ACC[2]), "+f"(ACC[3])               \
        : "r"(A0), "r"(A1), "r"(A2), "r"(A3), "r"(B0), "r"(B1))

#define OFF_ASL 2560
#define OFF_BSH 5120
#define OFF_BSL 7296
#define STG     9472
#define SMEM_BYTES (2 * STG * 4)

__device__ __forceinline__ void stage_chunk(unsigned* sm, int s,
    float4 ra0, float4 ra1, float4 rb0, float4 rb1,
    int arow, int acol, int brow, int bcol)
{
    unsigned* b = sm + s * STG;
    unsigned h0,l0,h1,l1,h2,l2,h3,l3;
    split_tf(ra0.x,h0,l0); split_tf(ra0.y,h1,l1);
    split_tf(ra0.z,h2,l2); split_tf(ra0.w,h3,l3);
    *(uint4*)&b[arow*20 + acol]            = make_uint4(h0,h1,h2,h3);
    *(uint4*)&b[OFF_ASL + arow*20 + acol]  = make_uint4(l0,l1,l2,l3);
    split_tf(ra1.x,h0,l0); split_tf(ra1.y,h1,l1);
    split_tf(ra1.z,h2,l2); split_tf(ra1.w,h3,l3);
    *(uint4*)&b[(arow+64)*20 + acol]           = make_uint4(h0,h1,h2,h3);
    *(uint4*)&b[OFF_ASL + (arow+64)*20 + acol] = make_uint4(l0,l1,l2,l3);
    split_tf(rb0.x,h0,l0); split_tf(rb0.y,h1,l1);
    split_tf(rb0.z,h2,l2); split_tf(rb0.w,h3,l3);
    *(uint4*)&b[OFF_BSH + brow*136 + bcol] = make_uint4(h0,h1,h2,h3);
    *(uint4*)&b[OFF_BSL + brow*136 + bcol] = make_uint4(l0,l1,l2,l3);
    split_tf(rb1.x,h0,l0); split_tf(rb1.y,h1,l1);
    split_tf(rb1.z,h2,l2); split_tf(rb1.w,h3,l3);
    *(uint4*)&b[OFF_BSH + brow*136 + bcol+4] = make_uint4(h0,h1,h2,h3);
    *(uint4*)&b[OFF_BSL + brow*136 + bcol+4] = make_uint4(l0,l1,l2,l3);
}

#define MMA_CHUNK(BASE)                                                        \
    _Pragma("unroll")                                                          \
    for (int kk = 0; kk < 16; kk += 8) {                                       \
        unsigned aH[4][4], aL[4][4], bH[4][2], bL[4][2];                       \
        _Pragma("unroll")                                                      \
        for (int mi = 0; mi < 4; mi++) {                                       \
            int rb = wm * 64 + mi * 16 + (lane >> 2);                          \
            int kc = kk + (lane & 3);                                          \
            aH[mi][0] = BASE[rb*20+kc];             aL[mi][0] = BASE[OFF_ASL+rb*20+kc]; \
            aH[mi][1] = BASE[(rb+8)*20+kc];         aL[mi][1] = BASE[OFF_ASL+(rb+8)*20+kc]; \
            aH[mi][2] = BASE[rb*20+kc+4];           aL[mi][2] = BASE[OFF_ASL+rb*20+kc+4]; \
            aH[mi][3] = BASE[(rb+8)*20+kc+4];       aL[mi][3] = BASE[OFF_ASL+(rb+8)*20+kc+4]; \
        }                                                                      \
        _Pragma("unroll")                                                      \
        for (int ni = 0; ni < 4; ni++) {                                       \
            int cb = wn * 32 + ni * 8 + (lane >> 2);                           \
            int kr = kk + (lane & 3);                                          \
            bH[ni][0] = BASE[OFF_BSH+kr*136+cb];     bL[ni][0] = BASE[OFF_BSL+kr*136+cb]; \
            bH[ni][1] = BASE[OFF_BSH+(kr+4)*136+cb]; bL[ni][1] = BASE[OFF_BSL+(kr+4)*136+cb]; \
        }                                                                      \
        _Pragma("unroll")                                                      \
        for (int mi = 0; mi < 4; mi++)                                         \
            _Pragma("unroll")                                                  \
            for (int ni = 0; ni < 4; ni++) {                                   \
                MMA_TF32(acc[mi][ni], aL[mi][0],aL[mi][1],aL[mi][2],aL[mi][3], \
                         bH[ni][0],bH[ni][1]);                                 \
                MMA_TF32(acc[mi][ni], aH[mi][0],aH[mi][1],aH[mi][2],aH[mi][3], \
                         bL[ni][0],bL[ni][1]);                                 \
                MMA_TF32(acc[mi][ni], aH[mi][0],aH[mi][1],aH[mi][2],aH[mi][3], \
                         bH[ni][0],bH[ni][1]);                                 \
            }                                                                  \
    }

#define P_BSH 2560
#define P_STG 4736
#define P_SMEM_BYTES (2 * P_STG * 4)

__device__ __forceinline__ void stage_chunk_hi(unsigned* sm, int s,
    float4 ra0, float4 ra1, float4 rb0, float4 rb1,
    int arow, int acol, int brow, int bcol)
{
    unsigned* b = sm + s * P_STG;
    *(uint4*)&b[arow*20 + acol] =
        make_uint4(f2tf(ra0.x), f2tf(ra0.y), f2tf(ra0.z), f2tf(ra0.w));
    *(uint4*)&b[(arow+64)*20 + acol] =
        make_uint4(f2tf(ra1.x), f2tf(ra1.y), f2tf(ra1.z), f2tf(ra1.w));
    *(uint4*)&b[P_BSH + brow*136 + bcol] =
        make_uint4(f2tf(rb0.x), f2tf(rb0.y), f2tf(rb0.z), f2tf(rb0.w));
    *(uint4*)&b[P_BSH + brow*136 + bcol+4] =
        make_uint4(f2tf(rb1.x), f2tf(rb1.y), f2tf(rb1.z), f2tf(rb1.w));
}

#define MMA_CHUNK_1(BASE)                                                      \
    _Pragma("unroll")                                                          \
    for (int kk = 0; kk < 16; kk += 8) {                                       \
        unsigned aH[4][4], bH[4][2];                                           \
        _Pragma("unroll")                                                      \
        for (int mi = 0; mi < 4; mi++) {                                       \
            int rb = wm * 64 + mi * 16 + (lane >> 2);                          \
            int kc = kk + (lane & 3);                                          \
            aH[mi][0] = BASE[rb*20+kc];                                        \
            aH[mi][1] = BASE[(rb+8)*20+kc];                                    \
            aH[mi][2] = BASE[rb*20+kc+4];                                      \
            aH[mi][3] = BASE[(rb+8)*20+kc+4];                                  \
        }                                                                      \
        _Pragma("unroll")                                                      \
        for (int ni = 0; ni < 4; ni++) {                                       \
            int cb = wn * 32 + ni * 8 + (lane >> 2);                           \
            int kr = kk + (lane & 3);                                          \
            bH[ni][0] = BASE[P_BSH+kr*136+cb];                                 \
            bH[ni][1] = BASE[P_BSH+(kr+4)*136+cb];                             \
        }                                                                      \
        _Pragma("unroll")                                                      \
        for (int mi = 0; mi < 4; mi++)                                         \
            _Pragma("unroll")                                                  \
            for (int ni = 0; ni < 4; ni++)                                     \
                MMA_TF32(acc[mi][ni], aH[mi][0],aH[mi][1],aH[mi][2],aH[mi][3], \
                         bH[ni][0],bH[ni][1]);                                 \
    }

// fused front GEMM: raw outputs only
__global__ void __launch_bounds__(256, 2)
gemm_front(const float* __restrict__ x,
           const float* __restrict__ w_s1,
           const float* __restrict__ w_s21,
           const float* __restrict__ w_raw, const float* __restrict__ b_raw,
           float* __restrict__ h1, float* __restrict__ h2,
           float* __restrict__ hf)
{
    extern __shared__ unsigned sm[];
    int sel  = blockIdx.x >> 1;
    int xcol = blockIdx.x & 1;
    const float* Bsel = (sel == 0) ? w_s1 : (sel == 1) ? w_s21 : w_raw;

    int tid  = threadIdx.x;
    int lane = tid & 31;
    int warp = tid >> 5;
    int wm = warp >> 2, wn = warp & 3;

    float acc[4][4][4];
#pragma unroll
    for (int mi = 0; mi < 4; mi++)
#pragma unroll
        for (int ni = 0; ni < 4; ni++)
#pragma unroll
            for (int r = 0; r < 4; r++) acc[mi][ni][r] = 0.0f;

    const float* Ab = x + (size_t)(blockIdx.y * 128) * 256;
    const float* Bb = Bsel + xcol * 128;

    int arow = tid >> 2, acol = (tid & 3) * 4;
    int brow = tid >> 4, bcol = (tid & 15) * 8;

    float4 ra0, ra1, rb0, rb1;
#define LOADF(K0)                                                               \
    ra0 = *(const float4*)(Ab + (size_t)arow * 256 + (K0) + acol);              \
    ra1 = *(const float4*)(Ab + (size_t)(arow + 64) * 256 + (K0) + acol);       \
    rb0 = *(const float4*)(Bb + (size_t)((K0) + brow) * 256 + bcol);            \
    rb1 = *(const float4*)(Bb + (size_t)((K0) + brow) * 256 + bcol + 4);

    LOADF(0)
    stage_chunk(sm, 0, ra0, ra1, rb0, rb1, arow, acol, brow, bcol);
    __syncthreads();
    int p = 0;
    for (int k0 = 0; k0 < 256; k0 += 16) {
        bool nxt = (k0 + 16) < 256;
        if (nxt) { LOADF(k0 + 16) }
        const unsigned* base = sm + p * STG;
        MMA_CHUNK(base)
        if (nxt) {
            stage_chunk(sm, p ^ 1, ra0, ra1, rb0, rb1, arow, acol, brow, bcol);
            __syncthreads();
        }
        p ^= 1;
    }

    int rbase = blockIdx.y * 128 + wm * 64 + (lane >> 2);
    int cloc  = xcol * 128 + wn * 32 + (lane & 3) * 2;
#pragma unroll
    for (int mi = 0; mi < 4; mi++)
#pragma unroll
        for (int ni = 0; ni < 4; ni++)
#pragma unroll
            for (int r = 0; r < 4; r++) {
                int row = rbase + mi * 16 + ((r >> 1) ? 8 : 0);
                int col = cloc + ni * 8 + (r & 1);
                float v = acc[mi][ni][r];
                if (sel == 0)      h1[(size_t)row * 256 + col] = v;
                else if (sel == 1) h2[(size_t)row * 256 + col] = v;
                else               hf[(size_t)row * 768 + 512 + col] = v + b_raw[col];
            }
}

// generic tf32x3, raw output only
__global__ void __launch_bounds__(256, 2)
gemm_tf32x3(const float* __restrict__ A, const float* __restrict__ B,
            float* __restrict__ C, int Nn, int Kk, int ldc)
{
    extern __shared__ unsigned sm[];
    int tid  = threadIdx.x;
    int lane = tid & 31;
    int warp = tid >> 5;
    int wm = warp >> 2, wn = warp & 3;

    float acc[4][4][4];
#pragma unroll
    for (int mi = 0; mi < 4; mi++)
#pragma unroll
        for (int ni = 0; ni < 4; ni++)
#pragma unroll
            for (int r = 0; r < 4; r++) acc[mi][ni][r] = 0.0f;

    const float* Ab = A + (size_t)(blockIdx.y * 128) * Kk;
    const float* Bb = B + blockIdx.x * 128;

    int arow = tid >> 2, acol = (tid & 3) * 4;
    int brow = tid >> 4, bcol = (tid & 15) * 8;

    float4 ra0, ra1, rb0, rb1;
#define LOADG(K0)                                                               \
    ra0 = *(const float4*)(Ab + (size_t)arow * Kk + (K0) + acol);               \
    ra1 = *(const float4*)(Ab + (size_t)(arow + 64) * Kk + (K0) + acol);        \
    rb0 = *(const float4*)(Bb + (size_t)((K0) + brow) * Nn + bcol);             \
    rb1 = *(const float4*)(Bb + (size_t)((K0) + brow) * Nn + bcol + 4);

    LOADG(0)
    stage_chunk(sm, 0, ra0, ra1, rb0, rb1, arow, acol, brow, bcol);
    __syncthreads();
    int p = 0;
    for (int k0 = 0; k0 < Kk; k0 += 16) {
        bool nxt = (k0 + 16) < Kk;
        if (nxt) { LOADG(k0 + 16) }
        const unsigned* base = sm + p * STG;
        MMA_CHUNK(base)
        if (nxt) {
            stage_chunk(sm, p ^ 1, ra0, ra1, rb0, rb1, arow, acol, brow, bcol);
            __syncthreads();
        }
        p ^= 1;
    }

    int rbase = blockIdx.y * 128 + wm * 64 + (lane >> 2);
    int cbase = blockIdx.x * 128 + wn * 32 + (lane & 3) * 2;
#pragma unroll
    for (int mi = 0; mi < 4; mi++)
#pragma unroll
        for (int ni = 0; ni < 4; ni++)
#pragma unroll
            for (int r = 0; r < 4; r++) {
                int row = rbase + mi * 16 + ((r >> 1) ? 8 : 0);
                int col = cbase + ni * 8 + (r & 1);
                C[(size_t)row * ldc + col] = acc[mi][ni][r];
            }
}

// masked pool GEMM — single-pass tf32
__global__ void __launch_bounds__(256, 2)
gemm_pool(const float* __restrict__ hf, const float* __restrict__ B,
          const float* __restrict__ bias, float* __restrict__ xt,
          const int* __restrict__ ridx, const int* __restrict__ pcnt)
{
    extern __shared__ unsigned sm[];
    int cnt = *pcnt;
    if ((int)(blockIdx.y * 128) >= cnt) return;

    int tid  = threadIdx.x;
    int lane = tid & 31;
    int warp = tid >> 5;
    int wm = warp >> 2, wn = warp & 3;

    float acc[4][4][4];
#pragma unroll
    for (int mi = 0; mi < 4; mi++)
#pragma unroll
        for (int ni = 0; ni < 4; ni++)
#pragma unroll
            for (int r = 0; r < 4; r++) acc[mi][ni][r] = 0.0f;

    int arow = tid >> 2, acol = (tid & 3) * 4;
    int brow = tid >> 4, bcol = (tid & 15) * 8;

    int gr0 = blockIdx.y * 128 + arow;
    int gr1 = gr0 + 64;
    const float* Ar0 = hf + (size_t)ridx[gr0 < cnt ? gr0 : cnt - 1] * 768;
    const float* Ar1 = hf + (size_t)ridx[gr1 < cnt ? gr1 : cnt - 1] * 768;
    const float* Bb = B + blockIdx.x * 128;

    float4 ra0, ra1, rb0, rb1;
#define LOADP(K0)                                                               \
    ra0 = *(const float4*)(Ar0 + (K0) + acol);                                  \
    ra1 = *(const float4*)(Ar1 + (K0) + acol);                                  \
    rb0 = *(const float4*)(Bb + (size_t)((K0) + brow) * 768 + bcol);            \
    rb1 = *(const float4*)(Bb + (size_t)((K0) + brow) * 768 + bcol + 4);

    LOADP(0)
    stage_chunk_hi(sm, 0, ra0, ra1, rb0, rb1, arow, acol, brow, bcol);
    __syncthreads();
    int p = 0;
    for (int k0 = 0; k0 < 768; k0 += 16) {
        bool nxt = (k0 + 16) < 768;
        if (nxt) { LOADP(k0 + 16) }
        const unsigned* base = sm + p * P_STG;
        MMA_CHUNK_1(base)
        if (nxt) {
            stage_chunk_hi(sm, p ^ 1, ra0, ra1, rb0, rb1, arow, acol, brow, bcol);
            __syncthreads();
        }
        p ^= 1;
    }

    int rbase = blockIdx.y * 128 + wm * 64 + (lane >> 2);
    int cbase = blockIdx.x * 128 + wn * 32 + (lane & 3) * 2;
#pragma unroll
    for (int mi = 0; mi < 4; mi++)
#pragma unroll
        for (int ni = 0; ni < 4; ni++)
#pragma unroll
            for (int r = 0; r < 4; r++) {
                int rg = rbase + mi * 16 + ((r >> 1) ? 8 : 0);
                int col = cbase + ni * 8 + (r & 1);
                if (rg < cnt) {
                    float v = acc[mi][ni][r] + bias[col];
                    v = 1.0f / (1.0f + expf(-v));
                    xt[(size_t)ridx[rg] * 768 + col] = v;
                }
            }
}

// ---------------- CSR aggregation (float4, self-term + bias + lrelu fused) ----------------
#define F4FMA(A, U, S) { (A).x += (U).x*(S); (A).y += (U).y*(S); (A).z += (U).z*(S); (A).w += (U).w*(S); }
__device__ __forceinline__ float lrelu1(float v) { return v > 0.0f ? v : 0.01f * v; }

__global__ void k_agg_csr2(const float* __restrict__ h1, const float* __restrict__ h2,
                           const int* __restrict__ off, const int* __restrict__ csrc,
                           const float* __restrict__ dinv,
                           const float* __restrict__ b1v, const float* __restrict__ b2v,
                           float* __restrict__ o1, float* __restrict__ o2) {
    int n = blockIdx.x * 8 + (threadIdx.x >> 5);
    int lane = threadIdx.x & 31;
    int c0 = lane * 8;
    float4 A1a = {0,0,0,0}, A1b = {0,0,0,0}, A2a = {0,0,0,0}, A2b = {0,0,0,0};
    int beg = off[n], end = off[n + 1];
    float dn = dinv[n];
    for (int j = beg; j < end; j++) {
        int s = csrc[j];
        float nrm = dn * dinv[s];
        const float4* r1 = (const float4*)(h1 + (size_t)s * 256 + c0);
        const float4* r2 = (const float4*)(h2 + (size_t)s * 256 + c0);
        float4 u0 = __ldg(r1), u1 = __ldg(r1 + 1);
        float4 v0 = __ldg(r2), v1 = __ldg(r2 + 1);
        F4FMA(A1a, u0, nrm); F4FMA(A1b, u1, nrm);
        F4FMA(A2a, v0, nrm); F4FMA(A2b, v1, nrm);
    }
    float dn2 = dn * dn;
    const float4* s1 = (const float4*)(h1 + (size_t)n * 256 + c0);
    const float4* s2 = (const float4*)(h2 + (size_t)n * 256 + c0);
    float4 x0 = __ldg(s1), x1 = __ldg(s1 + 1);
    float4 y0 = __ldg(s2), y1 = __ldg(s2 + 1);
    float4 ba0 = __ldg((const float4*)(b1v + c0)), ba1 = __ldg((const float4*)(b1v + c0 + 4));
    float4 bb0 = __ldg((const float4*)(b2v + c0)), bb1 = __ldg((const float4*)(b2v + c0 + 4));
    float4 o;
    o.x = lrelu1(x0.x*dn2 + ba0.x + A1a.x); o.y = lrelu1(x0.y*dn2 + ba0.y + A1a.y);
    o.z = lrelu1(x0.z*dn2 + ba0.z + A1a.z); o.w = lrelu1(x0.w*dn2 + ba0.w + A1a.w);
    *(float4*)(o1 + (size_t)n * 768 + c0) = o;
    o.x = lrelu1(x1.x*dn2 + ba1.x + A1b.x); o.y = lrelu1(x1.y*dn2 + ba1.y + A1b.y);
    o.z = lrelu1(x1.z*dn2 + ba1.z + A1b.z); o.w = lrelu1(x1.w*dn2 + ba1.w + A1b.w);
    *(float4*)(o1 + (size_t)n * 768 + c0 + 4) = o;
    o.x = lrelu1(y0.x*dn2 + bb0.x + A2a.x); o.y = lrelu1(y0.y*dn2 + bb0.y + A2a.y);
    o.z = lrelu1(y0.z*dn2 + bb0.z + A2a.z); o.w = lrelu1(y0.w*dn2 + bb0.w + A2a.w);
    *(float4*)(o2 + (size_t)n * 256 + c0) = o;
    o.x = lrelu1(y1.x*dn2 + bb1.x + A2b.x); o.y = lrelu1(y1.y*dn2 + bb1.y + A2b.y);
    o.z = lrelu1(y1.z*dn2 + bb1.z + A2b.z); o.w = lrelu1(y1.w*dn2 + bb1.w + A2b.w);
    *(float4*)(o2 + (size_t)n * 256 + c0 + 4) = o;
}
__global__ void k_agg_csr(const float* __restrict__ h, const int* __restrict__ off,
                          const int* __restrict__ csrc, const float* __restrict__ dinv,
                          const float* __restrict__ bv,
                          float* __restrict__ outp, int ldc) {
    int n = blockIdx.x * 8 + (threadIdx.x >> 5);
    int lane = threadIdx.x & 31;
    int c0 = lane * 8;
    float4 Aa = {0,0,0,0}, Ab4 = {0,0,0,0};
    int beg = off[n], end = off[n + 1];
    float dn = dinv[n];
    for (int j = beg; j < end; j++) {
        int s = csrc[j];
        float nrm = dn * dinv[s];
        const float4* r = (const float4*)(h + (size_t)s * 256 + c0);
        float4 u0 = __ldg(r), u1 = __ldg(r + 1);
        F4FMA(Aa, u0, nrm); F4FMA(Ab4, u1, nrm);
    }
    float dn2 = dn * dn;
    const float4* sp = (const float4*)(h + (size_t)n * 256 + c0);
    float4 x0 = __ldg(sp), x1 = __ldg(sp + 1);
    float4 b0 = __ldg((const float4*)(bv + c0)), b1 = __ldg((const float4*)(bv + c0 + 4));
    float4 o;
    o.x = lrelu1(x0.x*dn2 + b0.x + Aa.x); o.y = lrelu1(x0.y*dn2 + b0.y + Aa.y);
    o.z = lrelu1(x0.z*dn2 + b0.z + Aa.z); o.w = lrelu1(x0.w*dn2 + b0.w + Aa.w);
    *(float4*)(outp + (size_t)n * ldc + c0) = o;
    o.x = lrelu1(x1.x*dn2 + b1.x + Ab4.x); o.y = lrelu1(x1.y*dn2 + b1.y + Ab4.y);
    o.z = lrelu1(x1.z*dn2 + b1.z + Ab4.z); o.w = lrelu1(x1.w*dn2 + b1.w + Ab4.w);
    *(float4*)(outp + (size_t)n * ldc + c0 + 4) = o;
}

// ---------------- score path ----------------
__global__ void k_scorelin(const float* __restrict__ hf, const float* __restrict__ wpos,
                           const float* __restrict__ wneg,
                           float* __restrict__ splin, float* __restrict__ snlin) {
    __shared__ float swp[768], swn[768];
    for (int i = threadIdx.x; i < 768; i += blockDim.x) { swp[i] = wpos[i]; swn[i] = wneg[i]; }
    __syncthreads();
    int node = blockIdx.x * 8 + (threadIdx.x >> 5);
    int lane = threadIdx.x & 31;
    const float* r = hf + (size_t)node * 768;
    float sp = 0.0f, sn = 0.0f;
    for (int k = lane; k < 768; k += 32) {
        float v = r[k];
        sp += v * swp[k]; sn += v * swn[k];
    }
#pragma unroll
    for (int o = 16; o; o >>= 1) {
        sp += __shfl_down_sync(0xffffffffu, sp, o);
        sn += __shfl_down_sync(0xffffffffu, sn, o);
    }
    if (lane == 0) { splin[node] = sp; snlin[node] = sn; }
}
__global__ void k_score_csr(const float* __restrict__ splin, const float* __restrict__ snlin,
                            const int* __restrict__ off, const int* __restrict__ csrc,
                            const float* __restrict__ dinv,
                            const float* __restrict__ bpos, const float* __restrict__ bneg,
                            float* sp, float* sn, float* outp, float* outn) {
    int i = blockIdx.x * blockDim.x + threadIdx.x;
    if (i >= NN) return;
    float di = dinv[i];
    float vp = splin[i] * di * di + bpos[0];
    float vn = snlin[i] * di * di + bneg[0];
    int beg = off[i], end = off[i + 1];
    for (int j = beg; j < end; j++) {
        int s = csrc[j];
        float nrm = di * dinv[s];
        vp += splin[s] * nrm;
        vn += snlin[s] * nrm;
    }
    vp = 1.0f / (1.0f + expf(-vp));
    vn = 1.0f / (1.0f + expf(-vn));
    sp[i] = vp; sn[i] = vn;
    outp[i] = vp; outn[i] = vn;
}

// ---------------- top-k: masks + index lists ----------------
__global__ void k_topk(const float* __restrict__ spv, const float* __restrict__ snv,
                       unsigned char* __restrict__ mp, unsigned char* __restrict__ mn,
                       int* __restrict__ lists) {
    __shared__ float sv[NPGG];
    __shared__ int si[NPGG];
    int which = blockIdx.x >> 6;
    int g = blockIdx.x & 63;
    const float* score = which ? snv : spv;
    unsigned char* mask = which ? mn : mp;
    int t = threadIdx.x;
    sv[t] = score[g * NPGG + t];
    si[t] = t;
    __syncthreads();
    for (int k = 2; k <= NPGG; k <<= 1) {
        for (int j = k >> 1; j > 0; j >>= 1) {
            int ixj = t ^ j;
            if (ixj > t) {
                float va = sv[t], vb = sv[ixj];
                int ia = si[t], ib = si[ixj];
                bool firstBefore = (va > vb) || (va == vb && ia < ib);
                bool dirFwd = ((t & k) == 0);
                if (dirFwd ? !firstBefore : firstBefore) {
                    sv[t] = vb; sv[ixj] = va;
                    si[t] = ib; si[ixj] = ia;
                }
            }
            __syncthreads();
        }
    }
    mask[g * NPGG + si[t]] = (t < KSEL) ? 1 : 0;
    if (t < KSEL) lists[(which * GG + g) * KSEL + t] = si[t];
}

// ---------------- union compaction ----------------
__global__ void k_union(const unsigned char* __restrict__ mp,
                        const unsigned char* __restrict__ mn,
                        int* __restrict__ ridx, int* __restrict__ ucnt) {
    __shared__ int part[1024];
    int t = threadIdx.x;
    int base = t * 32;
    int sum = 0;
#pragma unroll
    for (int i = 0; i < 32; i++) sum += (mp[base + i] | mn[base + i]) ? 1 : 0;
    part[t] = sum;
    __syncthreads();
    for (int o = 1; o < 1024; o <<= 1) {
        int v = (t >= o) ? part[t - o] : 0;
        __syncthreads();
        part[t] += v;
        __syncthreads();
    }
    int pos = part[t] - sum;
#pragma unroll
    for (int i = 0; i < 32; i++)
        if (mp[base + i] | mn[base + i]) ridx[pos++] = base + i;
    if (t == 1023) *ucnt = part[1023];
}

// ---------------- readout via index lists ----------------
__global__ void k_readout(const float* __restrict__ xt, const int* __restrict__ lists,
                          float* __restrict__ eb) {
    __shared__ int sidx[KSEL];
    int z = blockIdx.z;
    int g = blockIdx.x;
    int f = blockIdx.y * 128 + threadIdx.x;
    const int* lst = lists + (z * GG + g) * KSEL;
    for (int i = threadIdx.x; i < KSEL; i += 128) sidx[i] = lst[i];
    __syncthreads();
    float* e = eb + z * (GG * 1536);
    float sum = 0.0f, mx = -INFINITY;
    const float* basep = xt + (size_t)g * NPGG * 768 + f;
    for (int n = 0; n < KSEL; n++) {
        float v = basep[(size_t)sidx[n] * 768];
        sum += v;
        mx = fmaxf(mx, v);
    }
    e[g * 1536 + f] = sum * (1.0f / (float)KSEL);
    e[g * 1536 + 768 + f] = mx;
}

// ---------------- MLP (batched pos/neg) ----------------
__global__ void k_mlp_lin(const float* __restrict__ inb, int in_set_stride,
                          const float* __restrict__ W, const float* __restrict__ b,
                          float* __restrict__ outb, int Kin, int Nout) {
    __shared__ float s_in[1536];
    int set = blockIdx.y;
    int row = blockIdx.x;
    const float* in = inb + (size_t)set * in_set_stride + (size_t)row * Kin;
    for (int k = threadIdx.x; k < Kin; k += blockDim.x) s_in[k] = in[k];
    __syncthreads();
    int j = threadIdx.x;
    if (j < Nout) {
        float s = b[j];
        for (int k = 0; k < Kin; k++) s += s_in[k] * W[k * Nout + j];
        outb[(size_t)(set * GG + row) * Nout + j] = s;
    }
}
__global__ void k_bn_relu(const float* __restrict__ zb, const float* __restrict__ g,
                          const float* __restrict__ be, const float* __restrict__ resb,
                          float* __restrict__ outb) {
    int c = blockIdx.x, r = threadIdx.x, set = blockIdx.y;
    const float* z = zb + (size_t)set * GG * 256;
    float v = z[r * 256 + c];
    __shared__ float sh[64];
    sh[r] = v; __syncthreads();
    for (int o = 32; o; o >>= 1) { if (r < o) sh[r] += sh[r + o]; __syncthreads(); }
    float mean = sh[0] * (1.0f / 64.0f);
    __syncthreads();
    sh[r] = v * v; __syncthreads();
    for (int o = 32; o; o >>= 1) { if (r < o) sh[r] += sh[r + o]; __syncthreads(); }
    float var = sh[0] * (1.0f / 64.0f) - mean * mean;
    float y = (v - mean) * rsqrtf(var + EPSB) * g[c] + be[c];
    y = fmaxf(y, 0.0f);
    if (resb) y += resb[(size_t)set * GG * 256 + r * 256 + c];
    outb[(size_t)set * GG * 256 + r * 256 + c] = y;
}
__global__ void k_logits_softmax(const float* __restrict__ ab, const float* __restrict__ w4,
                                 const float* __restrict__ b4,
                                 float* __restrict__ logits_pos,
                                 float* __restrict__ probs_pos,
                                 float* __restrict__ probs_neg) {
    int set = blockIdx.y;
    int row = blockIdx.x, j = threadIdx.x;
    const float* a = ab + (size_t)set * GG * 256;
    __shared__ float sl[CC];
    if (j < CC) {
        float s = b4[j];
        for (int k = 0; k < 256; k++) s += a[row * 256 + k] * w4[k * CC + j];
        sl[j] = s;
        if (set == 0) logits_pos[row * CC + j] = s;
    }
    __syncthreads();
    if (j < CC) {
        float mx = sl[0];
        for (int t = 1; t < CC; t++) mx = fmaxf(mx, sl[t]);
        float sum = 0.0f;
        for (int t = 0; t < CC; t++) sum += expf(sl[t] - mx);
        float pv = expf(sl[j] - mx) / sum;
        if (set == 0) probs_pos[row * CC + j] = pv;
        else          probs_neg[row * CC + j] = pv;
    }
}

// ---------------- host driver ----------------
static void* sym(const void* s) { void* p = nullptr; cudaGetSymbolAddress(&p, s); return p; }

extern "C" void kernel_launch(void* const* d_in, const int* in_sizes, int n_in,
                              void* d_out, int out_size) {
    const float* x     = (const float*)d_in[0];
    const void*  ei    = d_in[1];
    const void*  bt    = d_in[2];
    const float* w_s1  = (const float*)d_in[3];  const float* b_s1  = (const float*)d_in[4];
    const float* w_s21 = (const float*)d_in[5];  const float* b_s21 = (const float*)d_in[6];
    const float* w_s22 = (const float*)d_in[7];  const float* b_s22 = (const float*)d_in[8];
    const float* w_raw = (const float*)d_in[9];  const float* b_raw = (const float*)d_in[10];
    const float* w_pos = (const float*)d_in[11]; const float* b_pos = (const float*)d_in[12];
    const float* w_neg = (const float*)d_in[13]; const float* b_neg = (const float*)d_in[14];
    const float* w_pool= (const float*)d_in[15]; const float* b_pool= (const float*)d_in[16];
    const float* w1 = (const float*)d_in[17]; const float* b1 = (const float*)d_in[18];
    const float* g1 = (const float*)d_in[19]; const float* be1= (const float*)d_in[20];
    const float* w2 = (const float*)d_in[21]; const float* b2 = (const float*)d_in[22];
    const float* g2 = (const float*)d_in[23]; const float* be2= (const float*)d_in[24];
    const float* w3 = (const float*)d_in[25]; const float* b3 = (const float*)d_in[26];
    const float* g3 = (const float*)d_in[27]; const float* be3= (const float*)d_in[28];
    const float* w4 = (const float*)d_in[29]; const float* b4 = (const float*)d_in[30];

    float* dinv = (float*)sym(g_dinv);
    int* indeg  = (int*)sym(g_indeg);
    int* off    = (int*)sym(g_off);
    int* cur    = (int*)sym(g_cur);
    int* bsum   = (int*)sym(g_bsum);
    int* boff   = (int*)sym(g_boff);
    int* csrc   = (int*)sym(g_csrc);
    float* hbuf = (float*)sym(g_h);
    float* hbuf2= (float*)sym(g_h2);
    float* tbuf = (float*)sym(g_t);
    float* hf   = (float*)sym(g_hf);
    float* xt   = (float*)sym(g_xt);
    float* splin= (float*)sym(g_splin);
    float* snlin= (float*)sym(g_snlin);
    float* spv  = (float*)sym(g_sp);
    float* snv  = (float*)sym(g_sn);
    unsigned char* mp = (unsigned char*)sym(g_mp);
    unsigned char* mn = (unsigned char*)sym(g_mn);
    int* lists  = (int*)sym(g_list);
    int* ridx   = (int*)sym(g_ridx);
    int* ucnt   = (int*)sym(&g_ucnt);
    float* eb   = (float*)sym(g_e);
    float* zb   = (float*)sym(g_z);
    float* aA   = (float*)sym(g_aA);
    float* aB   = (float*)sym(g_aB);

    float* out = (float*)d_out;
    float* out_logits_pos = out;
    float* out_probs_pos  = out + 640;
    float* out_probs_neg  = out + 1280;
    float* out_score_pos  = out + 1920;
    float* out_score_neg  = out + 1920 + NN;
    float* out_batch      = out + 1920 + 2 * NN;

    cudaFuncSetAttribute(gemm_front,  cudaFuncAttributeMaxDynamicSharedMemorySize, SMEM_BYTES);
    cudaFuncSetAttribute(gemm_tf32x3, cudaFuncAttributeMaxDynamicSharedMemorySize, SMEM_BYTES);
    cudaFuncSetAttribute(gemm_pool,   cudaFuncAttributeMaxDynamicSharedMemorySize, P_SMEM_BYTES);

    // detect dtype + zero indeg (fused); batch passthrough early (off critical tail)
    k_init<<<NN / 256, 256>>>(bt, indeg);
    k_batch_out<<<NN / 256, 256>>>(bt, out_batch);

    // fused front GEMM (independent of CSR)
    dim3 gF(6, 256);
    gemm_front<<<gF, 256, SMEM_BYTES>>>(x, w_s1, w_s21, w_raw, b_raw, hbuf, hbuf2, hf);

    // CSR build (hierarchical scan)
    k_indeg<<<EE / 256, 256>>>(ei, indeg);
    k_scan1<<<128, 256>>>(indeg, off, cur, dinv, bsum);
    k_scan2<<<1, 128>>>(bsum, boff);
    k_scan3<<<128, 256>>>(off, boff);
    k_fill<<<EE / 256, 256>>>(ei, off, cur, csrc);

    // dual aggregation (self-term + bias + lrelu fused, float4)
    k_agg_csr2<<<NN / 8, 256>>>(hbuf, hbuf2, off, csrc, dinv, b_s1, b_s21, hf, tbuf);

    // s22 GEMM + aggregation
    dim3 gB256(2, 256);
    gemm_tf32x3<<<gB256, 256, SMEM_BYTES>>>(tbuf, w_s22, hbuf, 256, 256, 256);
    k_agg_csr<<<NN / 8, 256>>>(hbuf, off, csrc, dinv, b_s22, hf + 256, 768);

    // scores -> topk (+lists) -> union
    k_scorelin<<<NN / 8, 256>>>(hf, w_pos, w_neg, splin, snlin);
    k_score_csr<<<NN / 256, 256>>>(splin, snlin, off, csrc, dinv, b_pos, b_neg,
                                   spv, snv, out_score_pos, out_score_neg);
    k_topk<<<128, NPGG>>>(spv, snv, mp, mn, lists);
    k_union<<<1, 1024>>>(mp, mn, ridx, ucnt);

    // masked pool GEMM (single-pass tf32)
    dim3 gP(6, 256);
    gemm_pool<<<gP, 256, P_SMEM_BYTES>>>(hf, w_pool, b_pool, xt, ridx, ucnt);

    // readout via lists
    dim3 gr(GG, 6, 2);
    k_readout<<<gr, 128>>>(xt, lists, eb);

    // MLP (batched pos/neg)
    dim3 gl(GG, 2), gb(256, 2);
    k_mlp_lin<<<gl, 256>>>(eb, GG * 1536, w1, b1, zb, 1536, 256);
    k_bn_relu<<<gb, 64>>>(zb, g1, be1, nullptr, aA);
    k_mlp_lin<<<gl, 256>>>(aA, GG * 256, w2, b2, zb, 256, 256);
    k_bn_relu<<<gb, 64>>>(zb, g2, be2, aA, aB);
    k_mlp_lin<<<gl, 256>>>(aB, GG * 256, w3, b3, zb, 256, 256);
    k_bn_relu<<<gb, 64>>>(zb, g3, be3, aB, aA);
    k_logits_softmax<<<gl, 32>>>(aA, w4, b4, out_logits_pos, out_probs_pos, out_probs_neg);
}

// round 15
// speedup vs baseline: 1.5172x; 1.0353x over previous
#include <cuda_runtime.h>
#include <math.h>

#define NN   32768
#define EE   262144
#define GG   64
#define NPGG 512
#define KSEL 256
#define CC   10
#define EPSB 1e-5f

// ---------------- device scratch ----------------
__device__ float g_dinv[NN];
__device__ int   g_indeg[NN];
__device__ int   g_off[NN + 1];
__device__ int   g_cur[NN];
__device__ int   g_bsum[128];
__device__ int   g_boff[129];
__device__ int   g_csrc[EE];
__device__ float g_h[NN * 256];
__device__ float g_h2[NN * 256];
__device__ float g_t[NN * 256];
__device__ float g_hf[NN * 768];
__device__ float g_xt[NN * 768];
__device__ float g_splin[NN], g_snlin[NN];
__device__ float g_sp[NN], g_sn[NN];
__device__ unsigned char g_mp[NN], g_mn[NN];
__device__ int   g_list[2 * GG * KSEL];
__device__ int   g_ridx[NN];
__device__ int   g_ucnt;
__device__ float g_e[2 * GG * 1536];
__device__ float g_z[2 * GG * 256], g_aA[2 * GG * 256], g_aB[2 * GG * 256];
__device__ int   g_is64;

__device__ __forceinline__ int ld_idx(const void* p, long long i, int is64) {
    return is64 ? (int)((const long long*)p)[i] : ((const int*)p)[i];
}

// fused: dtype detect + zero indeg + batch passthrough
__global__ void k_init(const void* bt, int* indeg, float* out_batch) {
    int i = blockIdx.x * blockDim.x + threadIdx.x;
    if (i == 0) {
        int v = ((const int*)bt)[1025];
        g_is64 = (v == 2) ? 0 : 1;
    }
    __syncthreads();           // g_is64 visible? only within block 0 — use local detect instead
    if (i < NN) {
        indeg[i] = 0;
        // detect locally (cheap, avoids cross-block dependency on g_is64)
        int v = ((const int*)bt)[1025];
        int is64 = (v == 2) ? 0 : 1;
        out_batch[i] = (float)ld_idx(bt, i, is64);
    }
}
__global__ void k_indeg(const void* __restrict__ ei, int* indeg) {
    int e = blockIdx.x * blockDim.x + threadIdx.x;
    if (e >= EE) return;
    int d = ld_idx(ei, (long long)EE + e, g_is64);
    if ((unsigned)d < NN) atomicAdd(&indeg[d], 1);
}
// ---- hierarchical scan ----
__global__ void k_scan1(const int* __restrict__ indeg, int* __restrict__ off,
                        int* __restrict__ cur, float* __restrict__ dinv,
                        int* __restrict__ bsum) {
    __shared__ int sh[256];
    int t = threadIdx.x;
    int i = blockIdx.x * 256 + t;
    int v = indeg[i];
    dinv[i] = rsqrtf((float)v + 1.0f);
    cur[i] = 0;
    sh[t] = v;
    __syncthreads();
    for (int o = 1; o < 256; o <<= 1) {
        int add = (t >= o) ? sh[t - o] : 0;
        __syncthreads();
        sh[t] += add;
        __syncthreads();
    }
    off[i] = sh[t] - v;
    if (t == 255) bsum[blockIdx.x] = sh[255];
}
__global__ void k_scan2(const int* __restrict__ bsum, int* __restrict__ boff) {
    __shared__ int sh[128];
    int t = threadIdx.x;
    int v = bsum[t];
    sh[t] = v;
    __syncthreads();
    for (int o = 1; o < 128; o <<= 1) {
        int add = (t >= o) ? sh[t - o] : 0;
        __syncthreads();
        sh[t] += add;
        __syncthreads();
    }
    boff[t] = sh[t] - v;
    if (t == 127) boff[128] = sh[127];
}
__global__ void k_scan3(int* __restrict__ off, const int* __restrict__ boff) {
    int i = blockIdx.x * 256 + threadIdx.x;
    off[i] += boff[blockIdx.x];
    if (i == 0) off[NN] = boff[128];
}
__global__ void k_fill(const void* __restrict__ ei, const int* __restrict__ off,
                       int* __restrict__ cur, int* __restrict__ csrc) {
    int e = blockIdx.x * blockDim.x + threadIdx.x;
    if (e >= EE) return;
    int is64 = g_is64;
    int s = ld_idx(ei, e, is64);
    int d = ld_idx(ei, (long long)EE + e, is64);
    if ((unsigned)s >= NN || (unsigned)d >= NN) return;
    int pos = off[d] + atomicAdd(&cur[d], 1);
    csrc[pos] = s;
}

// ---------------- TF32 GEMM machinery ----------------
__device__ __forceinline__ unsigned f2tf(float f) {
    unsigned u;
    asm("cvt.rna.tf32.f32 %0, %1;" : "=r"(u) : "f"(f));
    return u;
}
__device__ __forceinline__ void split_tf(float v, unsigned& hi, unsigned& lo) {
    hi = f2tf(v);
    lo = f2tf(v - __uint_as_float(hi));
}
#define MMA_TF32(ACC, A0, A1, A2, A3, B0, B1)                                  \
    asm volatile(                                                              \
        "mma.sync.aligned.m16n8k8.row.col.f32.tf32.tf32.f32 "                  \
        "{%0,%1,%2,%3},{%4,%5,%6,%7},{%8,%9},{%0,%1,%2,%3};"                   \
        : "+f"(ACC[0]), "+f"(ACC[1]), "+f"(ACC[2]), "+f"(ACC[3])               \
        : "r"(A0), "r"(A1), "r"(A2), "r"(A3), "r"(B0), "r"(B1))

// ---- raw-f32 SMEM layout (convert at fragment load; bit-identical to hi/lo staging) ----
#define OFF_BSF 2560
#define STG_F   4736
#define SMEM_BYTES (2 * STG_F * 4)

__device__ __forceinline__ void stage_chunk_f(float* sm, int s,
    float4 ra0, float4 ra1, float4 rb0, float4 rb1,
    int arow, int acol, int brow, int bcol)
{
    float* b = sm + s * STG_F;
    *(float4*)&b[arow*20 + acol]          = ra0;
    *(float4*)&b[(arow+64)*20 + acol]     = ra1;
    *(float4*)&b[OFF_BSF + brow*136 + bcol]   = rb0;
    *(float4*)&b[OFF_BSF + brow*136 + bcol+4] = rb1;
}

// tf32x3 from raw f32 SMEM: load floats, split in regs, 3 MMA passes.
#define MMA_CHUNK_F(BASE)                                                      \
    _Pragma("unroll")                                                          \
    for (int kk = 0; kk < 16; kk += 8) {                                       \
        float af[4][4], bf[4][2];                                              \
        _Pragma("unroll")                                                      \
        for (int mi = 0; mi < 4; mi++) {                                       \
            int rb = wm * 64 + mi * 16 + (lane >> 2);                          \
            int kc = kk + (lane & 3);                                          \
            af[mi][0] = BASE[rb*20+kc];                                        \
            af[mi][1] = BASE[(rb+8)*20+kc];                                    \
            af[mi][2] = BASE[rb*20+kc+4];                                      \
            af[mi][3] = BASE[(rb+8)*20+kc+4];                                  \
        }                                                                      \
        _Pragma("unroll")                                                      \
        for (int ni = 0; ni < 4; ni++) {                                       \
            int cb = wn * 32 + ni * 8 + (lane >> 2);                           \
            int kr = kk + (lane & 3);                                          \
            bf[ni][0] = BASE[OFF_BSF+kr*136+cb];                               \
            bf[ni][1] = BASE[OFF_BSF+(kr+4)*136+cb];                           \
        }                                                                      \
        unsigned aH[4][4], aL[4][4], bH[4][2], bL[4][2];                       \
        _Pragma("unroll")                                                      \
        for (int mi = 0; mi < 4; mi++)                                         \
            _Pragma("unroll")                                                  \
            for (int q = 0; q < 4; q++) split_tf(af[mi][q], aH[mi][q], aL[mi][q]); \
        _Pragma("unroll")                                                      \
        for (int ni = 0; ni < 4; ni++) {                                       \
            split_tf(bf[ni][0], bH[ni][0], bL[ni][0]);                         \
            split_tf(bf[ni][1], bH[ni][1], bL[ni][1]);                         \
        }                                                                      \
        _Pragma("unroll")                                                      \
        for (int mi = 0; mi < 4; mi++)                                         \
            _Pragma("unroll")                                                  \
            for (int ni = 0; ni < 4; ni++) {                                   \
                MMA_TF32(acc[mi][ni], aL[mi][0],aL[mi][1],aL[mi][2],aL[mi][3], \
                         bH[ni][0],bH[ni][1]);                                 \
                MMA_TF32(acc[mi][ni], aH[mi][0],aH[mi][1],aH[mi][2],aH[mi][3], \
                         bL[ni][0],bL[ni][1]);                                 \
                MMA_TF32(acc[mi][ni], aH[mi][0],aH[mi][1],aH[mi][2],aH[mi][3], \
                         bH[ni][0],bH[ni][1]);                                 \
            }                                                                  \
    }

// single-pass tf32 (pool): same raw-f32 layout, hi only
#define MMA_CHUNK_1F(BASE)                                                     \
    _Pragma("unroll")                                                          \
    for (int kk = 0; kk < 16; kk += 8) {                                       \
        unsigned aH[4][4], bH[4][2];                                           \
        _Pragma("unroll")                                                      \
        for (int mi = 0; mi < 4; mi++) {                                       \
            int rb = wm * 64 + mi * 16 + (lane >> 2);                          \
            int kc = kk + (lane & 3);                                          \
            aH[mi][0] = f2tf(BASE[rb*20+kc]);                                  \
            aH[mi][1] = f2tf(BASE[(rb+8)*20+kc]);                              \
            aH[mi][2] = f2tf(BASE[rb*20+kc+4]);                                \
            aH[mi][3] = f2tf(BASE[(rb+8)*20+kc+4]);                            \
        }                                                                      \
        _Pragma("unroll")                                                      \
        for (int ni = 0; ni < 4; ni++) {                                       \
            int cb = wn * 32 + ni * 8 + (lane >> 2);                           \
            int kr = kk + (lane & 3);                                          \
            bH[ni][0] = f2tf(BASE[OFF_BSF+kr*136+cb]);                         \
            bH[ni][1] = f2tf(BASE[OFF_BSF+(kr+4)*136+cb]);                     \
        }                                                                      \
        _Pragma("unroll")                                                      \
        for (int mi = 0; mi < 4; mi++)                                         \
            _Pragma("unroll")                                                  \
            for (int ni = 0; ni < 4; ni++)                                     \
                MMA_TF32(acc[mi][ni], aH[mi][0],aH[mi][1],aH[mi][2],aH[mi][3], \
                         bH[ni][0],bH[ni][1]);                                 \
    }

// fused front GEMM: raw outputs only
__global__ void __launch_bounds__(256, 2)
gemm_front(const float* __restrict__ x,
           const float* __restrict__ w_s1,
           const float* __restrict__ w_s21,
           const float* __restrict__ w_raw, const float* __restrict__ b_raw,
           float* __restrict__ h1, float* __restrict__ h2,
           float* __restrict__ hf)
{
    extern __shared__ float smf[];
    int sel  = blockIdx.x >> 1;
    int xcol = blockIdx.x & 1;
    const float* Bsel = (sel == 0) ? w_s1 : (sel == 1) ? w_s21 : w_raw;

    int tid  = threadIdx.x;
    int lane = tid & 31;
    int warp = tid >> 5;
    int wm = warp >> 2, wn = warp & 3;

    float acc[4][4][4];
#pragma unroll
    for (int mi = 0; mi < 4; mi++)
#pragma unroll
        for (int ni = 0; ni < 4; ni++)
#pragma unroll
            for (int r = 0; r < 4; r++) acc[mi][ni][r] = 0.0f;

    const float* Ab = x + (size_t)(blockIdx.y * 128) * 256;
    const float* Bb = Bsel + xcol * 128;

    int arow = tid >> 2, acol = (tid & 3) * 4;
    int brow = tid >> 4, bcol = (tid & 15) * 8;

    float4 ra0, ra1, rb0, rb1;
#define LOADF(K0)                                                               \
    ra0 = *(const float4*)(Ab + (size_t)arow * 256 + (K0) + acol);              \
    ra1 = *(const float4*)(Ab + (size_t)(arow + 64) * 256 + (K0) + acol);       \
    rb0 = *(const float4*)(Bb + (size_t)((K0) + brow) * 256 + bcol);            \
    rb1 = *(const float4*)(Bb + (size_t)((K0) + brow) * 256 + bcol + 4);

    LOADF(0)
    stage_chunk_f(smf, 0, ra0, ra1, rb0, rb1, arow, acol, brow, bcol);
    __syncthreads();
    int p = 0;
    for (int k0 = 0; k0 < 256; k0 += 16) {
        bool nxt = (k0 + 16) < 256;
        if (nxt) { LOADF(k0 + 16) }
        const float* base = smf + p * STG_F;
        MMA_CHUNK_F(base)
        if (nxt) {
            stage_chunk_f(smf, p ^ 1, ra0, ra1, rb0, rb1, arow, acol, brow, bcol);
            __syncthreads();
        }
        p ^= 1;
    }

    int rbase = blockIdx.y * 128 + wm * 64 + (lane >> 2);
    int cloc  = xcol * 128 + wn * 32 + (lane & 3) * 2;
#pragma unroll
    for (int mi = 0; mi < 4; mi++)
#pragma unroll
        for (int ni = 0; ni < 4; ni++)
#pragma unroll
            for (int r = 0; r < 4; r++) {
                int row = rbase + mi * 16 + ((r >> 1) ? 8 : 0);
                int col = cloc + ni * 8 + (r & 1);
                float v = acc[mi][ni][r];
                if (sel == 0)      h1[(size_t)row * 256 + col] = v;
                else if (sel == 1) h2[(size_t)row * 256 + col] = v;
                else               hf[(size_t)row * 768 + 512 + col] = v + b_raw[col];
            }
}

// generic tf32x3, raw output only
__global__ void __launch_bounds__(256, 2)
gemm_tf32x3(const float* __restrict__ A, const float* __restrict__ B,
            float* __restrict__ C, int Nn, int Kk, int ldc)
{
    extern __shared__ float smf[];
    int tid  = threadIdx.x;
    int lane = tid & 31;
    int warp = tid >> 5;
    int wm = warp >> 2, wn = warp & 3;

    float acc[4][4][4];
#pragma unroll
    for (int mi = 0; mi < 4; mi++)
#pragma unroll
        for (int ni = 0; ni < 4; ni++)
#pragma unroll
            for (int r = 0; r < 4; r++) acc[mi][ni][r] = 0.0f;

    const float* Ab = A + (size_t)(blockIdx.y * 128) * Kk;
    const float* Bb = B + blockIdx.x * 128;

    int arow = tid >> 2, acol = (tid & 3) * 4;
    int brow = tid >> 4, bcol = (tid & 15) * 8;

    float4 ra0, ra1, rb0, rb1;
#define LOADG(K0)                                                               \
    ra0 = *(const float4*)(Ab + (size_t)arow * Kk + (K0) + acol);               \
    ra1 = *(const float4*)(Ab + (size_t)(arow + 64) * Kk + (K0) + acol);        \
    rb0 = *(const float4*)(Bb + (size_t)((K0) + brow) * Nn + bcol);             \
    rb1 = *(const float4*)(Bb + (size_t)((K0) + brow) * Nn + bcol + 4);

    LOADG(0)
    stage_chunk_f(smf, 0, ra0, ra1, rb0, rb1, arow, acol, brow, bcol);
    __syncthreads();
    int p = 0;
    for (int k0 = 0; k0 < Kk; k0 += 16) {
        bool nxt = (k0 + 16) < Kk;
        if (nxt) { LOADG(k0 + 16) }
        const float* base = smf + p * STG_F;
        MMA_CHUNK_F(base)
        if (nxt) {
            stage_chunk_f(smf, p ^ 1, ra0, ra1, rb0, rb1, arow, acol, brow, bcol);
            __syncthreads();
        }
        p ^= 1;
    }

    int rbase = blockIdx.y * 128 + wm * 64 + (lane >> 2);
    int cbase = blockIdx.x * 128 + wn * 32 + (lane & 3) * 2;
#pragma unroll
    for (int mi = 0; mi < 4; mi++)
#pragma unroll
        for (int ni = 0; ni < 4; ni++)
#pragma unroll
            for (int r = 0; r < 4; r++) {
                int row = rbase + mi * 16 + ((r >> 1) ? 8 : 0);
                int col = cbase + ni * 8 + (r & 1);
                C[(size_t)row * ldc + col] = acc[mi][ni][r];
            }
}

// masked pool GEMM — single-pass tf32 (raw-f32 SMEM)
__global__ void __launch_bounds__(256, 2)
gemm_pool(const float* __restrict__ hf, const float* __restrict__ B,
          const float* __restrict__ bias, float* __restrict__ xt,
          const int* __restrict__ ridx, const int* __restrict__ pcnt)
{
    extern __shared__ float smf[];
    int cnt = *pcnt;
    if ((int)(blockIdx.y * 128) >= cnt) return;

    int tid  = threadIdx.x;
    int lane = tid & 31;
    int warp = tid >> 5;
    int wm = warp >> 2, wn = warp & 3;

    float acc[4][4][4];
#pragma unroll
    for (int mi = 0; mi < 4; mi++)
#pragma unroll
        for (int ni = 0; ni < 4; ni++)
#pragma unroll
            for (int r = 0; r < 4; r++) acc[mi][ni][r] = 0.0f;

    int arow = tid >> 2, acol = (tid & 3) * 4;
    int brow = tid >> 4, bcol = (tid & 15) * 8;

    int gr0 = blockIdx.y * 128 + arow;
    int gr1 = gr0 + 64;
    const float* Ar0 = hf + (size_t)ridx[gr0 < cnt ? gr0 : cnt - 1] * 768;
    const float* Ar1 = hf + (size_t)ridx[gr1 < cnt ? gr1 : cnt - 1] * 768;
    const float* Bb = B + blockIdx.x * 128;

    float4 ra0, ra1, rb0, rb1;
#define LOADP(K0)                                                               \
    ra0 = *(const float4*)(Ar0 + (K0) + acol);                                  \
    ra1 = *(const float4*)(Ar1 + (K0) + acol);                                  \
    rb0 = *(const float4*)(Bb + (size_t)((K0) + brow) * 768 + bcol);            \
    rb1 = *(const float4*)(Bb + (size_t)((K0) + brow) * 768 + bcol + 4);

    LOADP(0)
    stage_chunk_f(smf, 0, ra0, ra1, rb0, rb1, arow, acol, brow, bcol);
    __syncthreads();
    int p = 0;
    for (int k0 = 0; k0 < 768; k0 += 16) {
        bool nxt = (k0 + 16) < 768;
        if (nxt) { LOADP(k0 + 16) }
        const float* base = smf + p * STG_F;
        MMA_CHUNK_1F(base)
        if (nxt) {
            stage_chunk_f(smf, p ^ 1, ra0, ra1, rb0, rb1, arow, acol, brow, bcol);
            __syncthreads();
        }
        p ^= 1;
    }

    int rbase = blockIdx.y * 128 + wm * 64 + (lane >> 2);
    int cbase = blockIdx.x * 128 + wn * 32 + (lane & 3) * 2;
#pragma unroll
    for (int mi = 0; mi < 4; mi++)
#pragma unroll
        for (int ni = 0; ni < 4; ni++)
#pragma unroll
            for (int r = 0; r < 4; r++) {
                int rg = rbase + mi * 16 + ((r >> 1) ? 8 : 0);
                int col = cbase + ni * 8 + (r & 1);
                if (rg < cnt) {
                    float v = acc[mi][ni][r] + bias[col];
                    v = 1.0f / (1.0f + expf(-v));
                    xt[(size_t)ridx[rg] * 768 + col] = v;
                }
            }
}

// ---------------- CSR aggregation (float4, self-term + bias + lrelu fused) ----------------
#define F4FMA(A, U, S) { (A).x += (U).x*(S); (A).y += (U).y*(S); (A).z += (U).z*(S); (A).w += (U).w*(S); }
__device__ __forceinline__ float lrelu1(float v) { return v > 0.0f ? v : 0.01f * v; }

__global__ void k_agg_csr2(const float* __restrict__ h1, const float* __restrict__ h2,
                           const int* __restrict__ off, const int* __restrict__ csrc,
                           const float* __restrict__ dinv,
                           const float* __restrict__ b1v, const float* __restrict__ b2v,
                           float* __restrict__ o1, float* __restrict__ o2) {
    int n = blockIdx.x * 8 + (threadIdx.x >> 5);
    int lane = threadIdx.x & 31;
    int c0 = lane * 8;
    float4 A1a = {0,0,0,0}, A1b = {0,0,0,0}, A2a = {0,0,0,0}, A2b = {0,0,0,0};
    int beg = off[n], end = off[n + 1];
    float dn = dinv[n];
    for (int j = beg; j < end; j++) {
        int s = csrc[j];
        float nrm = dn * dinv[s];
        const float4* r1 = (const float4*)(h1 + (size_t)s * 256 + c0);
        const float4* r2 = (const float4*)(h2 + (size_t)s * 256 + c0);
        float4 u0 = __ldg(r1), u1 = __ldg(r1 + 1);
        float4 v0 = __ldg(r2), v1 = __ldg(r2 + 1);
        F4FMA(A1a, u0, nrm); F4FMA(A1b, u1, nrm);
        F4FMA(A2a, v0, nrm); F4FMA(A2b, v1, nrm);
    }
    float dn2 = dn * dn;
    const float4* s1 = (const float4*)(h1 + (size_t)n * 256 + c0);
    const float4* s2 = (const float4*)(h2 + (size_t)n * 256 + c0);
    float4 x0 = __ldg(s1), x1 = __ldg(s1 + 1);
    float4 y0 = __ldg(s2), y1 = __ldg(s2 + 1);
    float4 ba0 = __ldg((const float4*)(b1v + c0)), ba1 = __ldg((const float4*)(b1v + c0 + 4));
    float4 bb0 = __ldg((const float4*)(b2v + c0)), bb1 = __ldg((const float4*)(b2v + c0 + 4));
    float4 o;
    o.x = lrelu1(x0.x*dn2 + ba0.x + A1a.x); o.y = lrelu1(x0.y*dn2 + ba0.y + A1a.y);
    o.z = lrelu1(x0.z*dn2 + ba0.z + A1a.z); o.w = lrelu1(x0.w*dn2 + ba0.w + A1a.w);
    *(float4*)(o1 + (size_t)n * 768 + c0) = o;
    o.x = lrelu1(x1.x*dn2 + ba1.x + A1b.x); o.y = lrelu1(x1.y*dn2 + ba1.y + A1b.y);
    o.z = lrelu1(x1.z*dn2 + ba1.z + A1b.z); o.w = lrelu1(x1.w*dn2 + ba1.w + A1b.w);
    *(float4*)(o1 + (size_t)n * 768 + c0 + 4) = o;
    o.x = lrelu1(y0.x*dn2 + bb0.x + A2a.x); o.y = lrelu1(y0.y*dn2 + bb0.y + A2a.y);
    o.z = lrelu1(y0.z*dn2 + bb0.z + A2a.z); o.w = lrelu1(y0.w*dn2 + bb0.w + A2a.w);
    *(float4*)(o2 + (size_t)n * 256 + c0) = o;
    o.x = lrelu1(y1.x*dn2 + bb1.x + A2b.x); o.y = lrelu1(y1.y*dn2 + bb1.y + A2b.y);
    o.z = lrelu1(y1.z*dn2 + bb1.z + A2b.z); o.w = lrelu1(y1.w*dn2 + bb1.w + A2b.w);
    *(float4*)(o2 + (size_t)n * 256 + c0 + 4) = o;
}
__global__ void k_agg_csr(const float* __restrict__ h, const int* __restrict__ off,
                          const int* __restrict__ csrc, const float* __restrict__ dinv,
                          const float* __restrict__ bv,
                          float* __restrict__ outp, int ldc) {
    int n = blockIdx.x * 8 + (threadIdx.x >> 5);
    int lane = threadIdx.x & 31;
    int c0 = lane * 8;
    float4 Aa = {0,0,0,0}, Ab4 = {0,0,0,0};
    int beg = off[n], end = off[n + 1];
    float dn = dinv[n];
    for (int j = beg; j < end; j++) {
        int s = csrc[j];
        float nrm = dn * dinv[s];
        const float4* r = (const float4*)(h + (size_t)s * 256 + c0);
        float4 u0 = __ldg(r), u1 = __ldg(r + 1);
        F4FMA(Aa, u0, nrm); F4FMA(Ab4, u1, nrm);
    }
    float dn2 = dn * dn;
    const float4* sp = (const float4*)(h + (size_t)n * 256 + c0);
    float4 x0 = __ldg(sp), x1 = __ldg(sp + 1);
    float4 b0 = __ldg((const float4*)(bv + c0)), b1 = __ldg((const float4*)(bv + c0 + 4));
    float4 o;
    o.x = lrelu1(x0.x*dn2 + b0.x + Aa.x); o.y = lrelu1(x0.y*dn2 + b0.y + Aa.y);
    o.z = lrelu1(x0.z*dn2 + b0.z + Aa.z); o.w = lrelu1(x0.w*dn2 + b0.w + Aa.w);
    *(float4*)(outp + (size_t)n * ldc + c0) = o;
    o.x = lrelu1(x1.x*dn2 + b1.x + Ab4.x); o.y = lrelu1(x1.y*dn2 + b1.y + Ab4.y);
    o.z = lrelu1(x1.z*dn2 + b1.z + Ab4.z); o.w = lrelu1(x1.w*dn2 + b1.w + Ab4.w);
    *(float4*)(outp + (size_t)n * ldc + c0 + 4) = o;
}

// ---------------- score path ----------------
__global__ void k_scorelin(const float* __restrict__ hf, const float* __restrict__ wpos,
                           const float* __restrict__ wneg,
                           float* __restrict__ splin, float* __restrict__ snlin) {
    __shared__ float swp[768], swn[768];
    for (int i = threadIdx.x; i < 768; i += blockDim.x) { swp[i] = wpos[i]; swn[i] = wneg[i]; }
    __syncthreads();
    int node = blockIdx.x * 8 + (threadIdx.x >> 5);
    int lane = threadIdx.x & 31;
    const float* r = hf + (size_t)node * 768;
    float sp = 0.0f, sn = 0.0f;
    for (int k = lane; k < 768; k += 32) {
        float v = r[k];
        sp += v * swp[k]; sn += v * swn[k];
    }
#pragma unroll
    for (int o = 16; o; o >>= 1) {
        sp += __shfl_down_sync(0xffffffffu, sp, o);
        sn += __shfl_down_sync(0xffffffffu, sn, o);
    }
    if (lane == 0) { splin[node] = sp; snlin[node] = sn; }
}
__global__ void k_score_csr(const float* __restrict__ splin, const float* __restrict__ snlin,
                            const int* __restrict__ off, const int* __restrict__ csrc,
                            const float* __restrict__ dinv,
                            const float* __restrict__ bpos, const float* __restrict__ bneg,
                            float* sp, float* sn, float* outp, float* outn) {
    int i = blockIdx.x * blockDim.x + threadIdx.x;
    if (i >= NN) return;
    float di = dinv[i];
    float vp = splin[i] * di * di + bpos[0];
    float vn = snlin[i] * di * di + bneg[0];
    int beg = off[i], end = off[i + 1];
    for (int j = beg; j < end; j++) {
        int s = csrc[j];
        float nrm = di * dinv[s];
        vp += splin[s] * nrm;
        vn += snlin[s] * nrm;
    }
    vp = 1.0f / (1.0f + expf(-vp));
    vn = 1.0f / (1.0f + expf(-vn));
    sp[i] = vp; sn[i] = vn;
    outp[i] = vp; outn[i] = vn;
}

// ---------------- top-k: masks + index lists ----------------
__global__ void k_topk(const float* __restrict__ spv, const float* __restrict__ snv,
                       unsigned char* __restrict__ mp, unsigned char* __restrict__ mn,
                       int* __restrict__ lists) {
    __shared__ float sv[NPGG];
    __shared__ int si[NPGG];
    int which = blockIdx.x >> 6;
    int g = blockIdx.x & 63;
    const float* score = which ? snv : spv;
    unsigned char* mask = which ? mn : mp;
    int t = threadIdx.x;
    sv[t] = score[g * NPGG + t];
    si[t] = t;
    __syncthreads();
    for (int k = 2; k <= NPGG; k <<= 1) {
        for (int j = k >> 1; j > 0; j >>= 1) {
            int ixj = t ^ j;
            if (ixj > t) {
                float va = sv[t], vb = sv[ixj];
                int ia = si[t], ib = si[ixj];
                bool firstBefore = (va > vb) || (va == vb && ia < ib);
                bool dirFwd = ((t & k) == 0);
                if (dirFwd ? !firstBefore : firstBefore) {
                    sv[t] = vb; sv[ixj] = va;
                    si[t] = ib; si[ixj] = ia;
                }
            }
            __syncthreads();
        }
    }
    mask[g * NPGG + si[t]] = (t < KSEL) ? 1 : 0;
    if (t < KSEL) lists[(which * GG + g) * KSEL + t] = si[t];
}

// ---------------- union compaction ----------------
__global__ void k_union(const unsigned char* __restrict__ mp,
                        const unsigned char* __restrict__ mn,
                        int* __restrict__ ridx, int* __restrict__ ucnt) {
    __shared__ int part[1024];
    int t = threadIdx.x;
    int base = t * 32;
    int sum = 0;
#pragma unroll
    for (int i = 0; i < 32; i++) sum += (mp[base + i] | mn[base + i]) ? 1 : 0;
    part[t] = sum;
    __syncthreads();
    for (int o = 1; o < 1024; o <<= 1) {
        int v = (t >= o) ? part[t - o] : 0;
        __syncthreads();
        part[t] += v;
        __syncthreads();
    }
    int pos = part[t] - sum;
#pragma unroll
    for (int i = 0; i < 32; i++)
        if (mp[base + i] | mn[base + i]) ridx[pos++] = base + i;
    if (t == 1023) *ucnt = part[1023];
}

// ---------------- readout via index lists ----------------
__global__ void k_readout(const float* __restrict__ xt, const int* __restrict__ lists,
                          float* __restrict__ eb) {
    __shared__ int sidx[KSEL];
    int z = blockIdx.z;
    int g = blockIdx.x;
    int f = blockIdx.y * 128 + threadIdx.x;
    const int* lst = lists + (z * GG + g) * KSEL;
    for (int i = threadIdx.x; i < KSEL; i += 128) sidx[i] = lst[i];
    __syncthreads();
    float* e = eb + z * (GG * 1536);
    float sum = 0.0f, mx = -INFINITY;
    const float* basep = xt + (size_t)g * NPGG * 768 + f;
    for (int n = 0; n < KSEL; n++) {
        float v = basep[(size_t)sidx[n] * 768];
        sum += v;
        mx = fmaxf(mx, v);
    }
    e[g * 1536 + f] = sum * (1.0f / (float)KSEL);
    e[g * 1536 + 768 + f] = mx;
}

// ---------------- MLP (batched pos/neg) ----------------
__global__ void k_mlp_lin(const float* __restrict__ inb, int in_set_stride,
                          const float* __restrict__ W, const float* __restrict__ b,
                          float* __restrict__ outb, int Kin, int Nout) {
    __shared__ float s_in[1536];
    int set = blockIdx.y;
    int row = blockIdx.x;
    const float* in = inb + (size_t)set * in_set_stride + (size_t)row * Kin;
    for (int k = threadIdx.x; k < Kin; k += blockDim.x) s_in[k] = in[k];
    __syncthreads();
    int j = threadIdx.x;
    if (j < Nout) {
        float s = b[j];
        for (int k = 0; k < Kin; k++) s += s_in[k] * W[k * Nout + j];
        outb[(size_t)(set * GG + row) * Nout + j] = s;
    }
}
__global__ void k_bn_relu(const float* __restrict__ zb, const float* __restrict__ g,
                          const float* __restrict__ be, const float* __restrict__ resb,
                          float* __restrict__ outb) {
    int c = blockIdx.x, r = threadIdx.x, set = blockIdx.y;
    const float* z = zb + (size_t)set * GG * 256;
    float v = z[r * 256 + c];
    __shared__ float sh[64];
    sh[r] = v; __syncthreads();
    for (int o = 32; o; o >>= 1) { if (r < o) sh[r] += sh[r + o]; __syncthreads(); }
    float mean = sh[0] * (1.0f / 64.0f);
    __syncthreads();
    sh[r] = v * v; __syncthreads();
    for (int o = 32; o; o >>= 1) { if (r < o) sh[r] += sh[r + o]; __syncthreads(); }
    float var = sh[0] * (1.0f / 64.0f) - mean * mean;
    float y = (v - mean) * rsqrtf(var + EPSB) * g[c] + be[c];
    y = fmaxf(y, 0.0f);
    if (resb) y += resb[(size_t)set * GG * 256 + r * 256 + c];
    outb[(size_t)set * GG * 256 + r * 256 + c] = y;
}
__global__ void k_logits_softmax(const float* __restrict__ ab, const float* __restrict__ w4,
                                 const float* __restrict__ b4,
                                 float* __restrict__ logits_pos,
                                 float* __restrict__ probs_pos,
                                 float* __restrict__ probs_neg) {
    int set = blockIdx.y;
    int row = blockIdx.x, j = threadIdx.x;
    const float* a = ab + (size_t)set * GG * 256;
    __shared__ float sl[CC];
    if (j < CC) {
        float s = b4[j];
        for (int k = 0; k < 256; k++) s += a[row * 256 + k] * w4[k * CC + j];
        sl[j] = s;
        if (set == 0) logits_pos[row * CC + j] = s;
    }
    __syncthreads();
    if (j < CC) {
        float mx = sl[0];
        for (int t = 1; t < CC; t++) mx = fmaxf(mx, sl[t]);
        float sum = 0.0f;
        for (int t = 0; t < CC; t++) sum += expf(sl[t] - mx);
        float pv = expf(sl[j] - mx) / sum;
        if (set == 0) probs_pos[row * CC + j] = pv;
        else          probs_neg[row * CC + j] = pv;
    }
}

// ---------------- host driver ----------------
static void* sym(const void* s) { void* p = nullptr; cudaGetSymbolAddress(&p, s); return p; }

extern "C" void kernel_launch(void* const* d_in, const int* in_sizes, int n_in,
                              void* d_out, int out_size) {
    const float* x     = (const float*)d_in[0];
    const void*  ei    = d_in[1];
    const void*  bt    = d_in[2];
    const float* w_s1  = (const float*)d_in[3];  const float* b_s1  = (const float*)d_in[4];
    const float* w_s21 = (const float*)d_in[5];  const float* b_s21 = (const float*)d_in[6];
    const float* w_s22 = (const float*)d_in[7];  const float* b_s22 = (const float*)d_in[8];
    const float* w_raw = (const float*)d_in[9];  const float* b_raw = (const float*)d_in[10];
    const float* w_pos = (const float*)d_in[11]; const float* b_pos = (const float*)d_in[12];
    const float* w_neg = (const float*)d_in[13]; const float* b_neg = (const float*)d_in[14];
    const float* w_pool= (const float*)d_in[15]; const float* b_pool= (const float*)d_in[16];
    const float* w1 = (const float*)d_in[17]; const float* b1 = (const float*)d_in[18];
    const float* g1 = (const float*)d_in[19]; const float* be1= (const float*)d_in[20];
    const float* w2 = (const float*)d_in[21]; const float* b2 = (const float*)d_in[22];
    const float* g2 = (const float*)d_in[23]; const float* be2= (const float*)d_in[24];
    const float* w3 = (const float*)d_in[25]; const float* b3 = (const float*)d_in[26];
    const float* g3 = (const float*)d_in[27]; const float* be3= (const float*)d_in[28];
    const float* w4 = (const float*)d_in[29]; const float* b4 = (const float*)d_in[30];

    float* dinv = (float*)sym(g_dinv);
    int* indeg  = (int*)sym(g_indeg);
    int* off    = (int*)sym(g_off);
    int* cur    = (int*)sym(g_cur);
    int* bsum   = (int*)sym(g_bsum);
    int* boff   = (int*)sym(g_boff);
    int* csrc   = (int*)sym(g_csrc);
    float* hbuf = (float*)sym(g_h);
    float* hbuf2= (float*)sym(g_h2);
    float* tbuf = (float*)sym(g_t);
    float* hf   = (float*)sym(g_hf);
    float* xt   = (float*)sym(g_xt);
    float* splin= (float*)sym(g_splin);
    float* snlin= (float*)sym(g_snlin);
    float* spv  = (float*)sym(g_sp);
    float* snv  = (float*)sym(g_sn);
    unsigned char* mp = (unsigned char*)sym(g_mp);
    unsigned char* mn = (unsigned char*)sym(g_mn);
    int* lists  = (int*)sym(g_list);
    int* ridx   = (int*)sym(g_ridx);
    int* ucnt   = (int*)sym(&g_ucnt);
    float* eb   = (float*)sym(g_e);
    float* zb   = (float*)sym(g_z);
    float* aA   = (float*)sym(g_aA);
    float* aB   = (float*)sym(g_aB);

    float* out = (float*)d_out;
    float* out_logits_pos = out;
    float* out_probs_pos  = out + 640;
    float* out_probs_neg  = out + 1280;
    float* out_score_pos  = out + 1920;
    float* out_score_neg  = out + 1920 + NN;
    float* out_batch      = out + 1920 + 2 * NN;

    cudaFuncSetAttribute(gemm_front,  cudaFuncAttributeMaxDynamicSharedMemorySize, SMEM_BYTES);
    cudaFuncSetAttribute(gemm_tf32x3, cudaFuncAttributeMaxDynamicSharedMemorySize, SMEM_BYTES);
    cudaFuncSetAttribute(gemm_pool,   cudaFuncAttributeMaxDynamicSharedMemorySize, SMEM_BYTES);

    // detect dtype + zero indeg + batch passthrough (fused)
    k_init<<<NN / 256, 256>>>(bt, indeg, out_batch);

    // fused front GEMM (independent of CSR)
    dim3 gF(6, 256);
    gemm_front<<<gF, 256, SMEM_BYTES>>>(x, w_s1, w_s21, w_raw, b_raw, hbuf, hbuf2, hf);

    // CSR build (hierarchical scan)
    k_indeg<<<EE / 256, 256>>>(ei, indeg);
    k_scan1<<<128, 256>>>(indeg, off, cur, dinv, bsum);
    k_scan2<<<1, 128>>>(bsum, boff);
    k_scan3<<<128, 256>>>(off, boff);
    k_fill<<<EE / 256, 256>>>(ei, off, cur, csrc);

    // dual aggregation (self-term + bias + lrelu fused, float4)
    k_agg_csr2<<<NN / 8, 256>>>(hbuf, hbuf2, off, csrc, dinv, b_s1, b_s21, hf, tbuf);

    // s22 GEMM + aggregation
    dim3 gB256(2, 256);
    gemm_tf32x3<<<gB256, 256, SMEM_BYTES>>>(tbuf, w_s22, hbuf, 256, 256, 256);
    k_agg_csr<<<NN / 8, 256>>>(hbuf, off, csrc, dinv, b_s22, hf + 256, 768);

    // scores -> topk (+lists) -> union
    k_scorelin<<<NN / 8, 256>>>(hf, w_pos, w_neg, splin, snlin);
    k_score_csr<<<NN / 256, 256>>>(splin, snlin, off, csrc, dinv, b_pos, b_neg,
                                   spv, snv, out_score_pos, out_score_neg);
    k_topk<<<128, NPGG>>>(spv, snv, mp, mn, lists);
    k_union<<<1, 1024>>>(mp, mn, ridx, ucnt);

    // masked pool GEMM (single-pass tf32)
    dim3 gP(6, 256);
    gemm_pool<<<gP, 256, SMEM_BYTES>>>(hf, w_pool, b_pool, xt, ridx, ucnt);

    // readout via lists
    dim3 gr(GG, 6, 2);
    k_readout<<<gr, 128>>>(xt, lists, eb);

    // MLP (batched pos/neg)
    dim3 gl(GG, 2), gb(256, 2);
    k_mlp_lin<<<gl, 256>>>(eb, GG * 1536, w1, b1, zb, 1536, 256);
    k_bn_relu<<<gb, 64>>>(zb, g1, be1, nullptr, aA);
    k_mlp_lin<<<gl, 256>>>(aA, GG * 256, w2, b2, zb, 256, 256);
    k_bn_relu<<<gb, 64>>>(zb, g2, be2, aA, aB);
    k_mlp_lin<<<gl, 256>>>(aB, GG * 256, w3, b3, zb, 256, 256);
    k_bn_relu<<<gb, 64>>>(zb, g3, be3, aB, aA);
    k_logits_softmax<<<gl, 32>>>(aA, w4, b4, out_logits_pos, out_probs_pos, out_probs_neg);
}